// round 2
// baseline (speedup 1.0000x reference)
#include <cuda_runtime.h>
#include <math.h>

#define BATCH 8
#define LSEQ  1024
#define HID   768
#define NH    12
#define DH    64
#define MLPD  3072
#define MROWS (BATCH*LSEQ)   // 8192
#define NHEADS_TOT (BATCH*NH) // 96

// ---------------- static scratch (no allocations allowed) ----------------
__device__ float g_Q  [MROWS*HID];
__device__ float g_K  [MROWS*HID];
__device__ float g_Qh [MROWS*HID];
__device__ float g_Kh [MROWS*HID];
__device__ float g_S  [(size_t)NHEADS_TOT*LSEQ*LSEQ];   // 402 MB
__device__ float g_Ch [MROWS*HID];   // head-major ctx
__device__ float g_Ctx[MROWS*HID];   // interleaved ctx
__device__ float g_y  [MROWS*HID];
__device__ float g_x1 [MROWS*HID];
__device__ float g_Hf [(size_t)MROWS*MLPD];              // 100 MB
__device__ float g_y2 [MROWS*HID];

// ---------------- helpers ----------------
__device__ __forceinline__ float gelu_f(float v) {
    return 0.5f * v * (1.0f + erff(v * 0.7071067811865475f));
}

enum { EPI_NONE = 0, EPI_RES = 1, EPI_BIAS_GELU = 2, EPI_BIAS_RES = 3 };

// ---------------- generic 128x128x8 SGEMM, C = A(MxK) @ B(KxN) ----------------
template<int EPI>
__global__ __launch_bounds__(256) void sgemm128(
    const float* __restrict__ A, const float* __restrict__ B, float* __restrict__ C,
    const float* __restrict__ bias, const float* __restrict__ res,
    int M, int N, int K)
{
    __shared__ float As[8][128];
    __shared__ float Bs[8][128];

    const int tid = threadIdx.x;
    const int bx = blockIdx.x;   // N tile
    const int by = blockIdx.y;   // M tile

    // A tile load: 128 rows x 8 cols -> 256 float4 (2 float4 per row)
    const int arow = tid >> 1;
    const int acol = (tid & 1) * 4;
    // B tile load: 8 rows x 128 cols -> 256 float4
    const int brow = tid >> 5;
    const int bcol = (tid & 31) * 4;

    const float* Aptr = A + (size_t)(by * 128 + arow) * K + acol;
    const float* Bptr = B + (size_t)brow * N + bx * 128 + bcol;

    const int trow = (tid >> 4) * 8;
    const int tcol = (tid & 15) * 8;

    float acc[8][8];
    #pragma unroll
    for (int i = 0; i < 8; i++)
        #pragma unroll
        for (int j = 0; j < 8; j++) acc[i][j] = 0.0f;

    for (int k0 = 0; k0 < K; k0 += 8) {
        float4 a4 = *(const float4*)Aptr;  Aptr += 8;
        float4 b4 = *(const float4*)Bptr;  Bptr += (size_t)8 * N;
        As[acol + 0][arow] = a4.x;
        As[acol + 1][arow] = a4.y;
        As[acol + 2][arow] = a4.z;
        As[acol + 3][arow] = a4.w;
        *(float4*)&Bs[brow][bcol] = b4;
        __syncthreads();

        #pragma unroll
        for (int k = 0; k < 8; k++) {
            float ar[8], br[8];
            *(float4*)(ar)     = *(const float4*)&As[k][trow];
            *(float4*)(ar + 4) = *(const float4*)&As[k][trow + 4];
            *(float4*)(br)     = *(const float4*)&Bs[k][tcol];
            *(float4*)(br + 4) = *(const float4*)&Bs[k][tcol + 4];
            #pragma unroll
            for (int i = 0; i < 8; i++)
                #pragma unroll
                for (int j = 0; j < 8; j++)
                    acc[i][j] = fmaf(ar[i], br[j], acc[i][j]);
        }
        __syncthreads();
    }

    const int crow0 = by * 128 + trow;
    const int ccol0 = bx * 128 + tcol;
    #pragma unroll
    for (int i = 0; i < 8; i++) {
        const size_t rbase = (size_t)(crow0 + i) * N;
        #pragma unroll
        for (int j = 0; j < 8; j++) {
            const int c = ccol0 + j;
            float v = acc[i][j];
            if (EPI == EPI_RES)        v += res[rbase + c];
            if (EPI == EPI_BIAS_GELU)  v = gelu_f(v + bias[c]);
            if (EPI == EPI_BIAS_RES)   v += bias[c] + res[rbase + c];
            C[rbase + c] = v;
        }
    }
}

// ---------------- permutes: interleaved (h = d*12 + n) <-> head-major ----------------
__global__ void to_head_k(const float* __restrict__ X, float* __restrict__ Xh) {
    int idx = blockIdx.x * blockDim.x + threadIdx.x;   // over head-major layout
    if (idx >= MROWS * HID) return;
    int d = idx & 63;
    int l = (idx >> 6) & 1023;
    int z = idx >> 16;                 // b*NH + n
    int n = z % NH, b = z / NH;
    Xh[idx] = X[(size_t)(b * LSEQ + l) * HID + d * NH + n];
}

__global__ void from_head_k(const float* __restrict__ Xh, float* __restrict__ X) {
    int idx = blockIdx.x * blockDim.x + threadIdx.x;   // over interleaved layout
    if (idx >= MROWS * HID) return;
    int h = idx % HID;
    int row = idx / HID;
    int l = row & 1023, b = row >> 10;
    int d = h / NH, n = h % NH;
    X[idx] = Xh[((size_t)(b * NH + n) * LSEQ + l) * DH + d];
}

// ---------------- attention scores: S[z][l][m] = 0.125 * Qh[z][l]·Kh[z][m] ----------------
__global__ __launch_bounds__(256) void attn_scores_k(
    const float* __restrict__ Qh, const float* __restrict__ Kh, float* __restrict__ S)
{
    const int z = blockIdx.z;
    const int lt = blockIdx.y, mt = blockIdx.x;
    const float* Q  = Qh + ((size_t)z * LSEQ + lt * 64) * DH;
    const float* Kp = Kh + ((size_t)z * LSEQ + mt * 64) * DH;

    __shared__ float Qs[64][DH + 1];
    __shared__ float Ks[64][DH + 1];
    const int tid = threadIdx.x;

    for (int i = tid; i < 64 * 16; i += 256) {
        int r = i >> 4, c = (i & 15) << 2;
        float4 q4 = *(const float4*)(Q + r * DH + c);
        Qs[r][c] = q4.x; Qs[r][c+1] = q4.y; Qs[r][c+2] = q4.z; Qs[r][c+3] = q4.w;
        float4 k4 = *(const float4*)(Kp + r * DH + c);
        Ks[r][c] = k4.x; Ks[r][c+1] = k4.y; Ks[r][c+2] = k4.z; Ks[r][c+3] = k4.w;
    }
    __syncthreads();

    const int tr = (tid >> 4) << 2;
    const int tc = (tid & 15) << 2;
    float acc[4][4];
    #pragma unroll
    for (int i = 0; i < 4; i++)
        #pragma unroll
        for (int j = 0; j < 4; j++) acc[i][j] = 0.0f;

    #pragma unroll 8
    for (int d = 0; d < DH; d++) {
        float q[4], k[4];
        #pragma unroll
        for (int i = 0; i < 4; i++) q[i] = Qs[tr + i][d];
        #pragma unroll
        for (int j = 0; j < 4; j++) k[j] = Ks[tc + j][d];
        #pragma unroll
        for (int i = 0; i < 4; i++)
            #pragma unroll
            for (int j = 0; j < 4; j++)
                acc[i][j] = fmaf(q[i], k[j], acc[i][j]);
    }

    float* Sp = S + (size_t)z * LSEQ * LSEQ;
    #pragma unroll
    for (int i = 0; i < 4; i++)
        #pragma unroll
        for (int j = 0; j < 4; j++)
            Sp[(size_t)(lt * 64 + tr + i) * LSEQ + (mt * 64 + tc + j)] = acc[i][j] * 0.125f;
}

// ---------------- row softmax over 1024 columns ----------------
__global__ __launch_bounds__(256) void softmax_rows_k(float* __restrict__ S) {
    float* p = S + (size_t)blockIdx.x * LSEQ;
    const int tid = threadIdx.x;
    __shared__ float sh[8];

    float m = -3.0e38f;
    for (int c = tid; c < LSEQ; c += 256) m = fmaxf(m, p[c]);
    #pragma unroll
    for (int o = 16; o; o >>= 1) m = fmaxf(m, __shfl_xor_sync(0xffffffffu, m, o));
    if ((tid & 31) == 0) sh[tid >> 5] = m;
    __syncthreads();
    if (tid == 0) {
        float v = sh[0];
        #pragma unroll
        for (int i = 1; i < 8; i++) v = fmaxf(v, sh[i]);
        sh[0] = v;
    }
    __syncthreads();
    m = sh[0];
    __syncthreads();

    float s = 0.0f;
    for (int c = tid; c < LSEQ; c += 256) {
        float e = expf(p[c] - m);
        p[c] = e;
        s += e;
    }
    #pragma unroll
    for (int o = 16; o; o >>= 1) s += __shfl_xor_sync(0xffffffffu, s, o);
    if ((tid & 31) == 0) sh[tid >> 5] = s;
    __syncthreads();
    if (tid == 0) {
        float v = 0.0f;
        #pragma unroll
        for (int i = 0; i < 8; i++) v += sh[i];
        sh[0] = v;
    }
    __syncthreads();
    const float inv = 1.0f / sh[0];
    for (int c = tid; c < LSEQ; c += 256) p[c] *= inv;
}

// ---------------- ctx: Ch[z][l][d] = sum_m P[z][l][m] * Kh[z][m][d] ----------------
__global__ __launch_bounds__(256) void attn_ctx_k(
    const float* __restrict__ S, const float* __restrict__ Kh, float* __restrict__ Ch)
{
    const int z = blockIdx.y;
    const int lt = blockIdx.x;
    const float* Sp = S + (size_t)z * LSEQ * LSEQ + (size_t)(lt * 64) * LSEQ;
    const float* Kp = Kh + (size_t)z * LSEQ * DH;

    __shared__ float Ps[64][33];
    __shared__ float Ks[32][DH + 1];
    const int tid = threadIdx.x;
    const int tr = (tid >> 4) << 2;
    const int tc = (tid & 15) << 2;

    float acc[4][4];
    #pragma unroll
    for (int i = 0; i < 4; i++)
        #pragma unroll
        for (int j = 0; j < 4; j++) acc[i][j] = 0.0f;

    for (int m0 = 0; m0 < LSEQ; m0 += 32) {
        for (int i = tid; i < 64 * 8; i += 256) {
            int r = i >> 3, c = (i & 7) << 2;
            float4 v = *(const float4*)(Sp + (size_t)r * LSEQ + m0 + c);
            Ps[r][c] = v.x; Ps[r][c+1] = v.y; Ps[r][c+2] = v.z; Ps[r][c+3] = v.w;
        }
        for (int i = tid; i < 32 * 16; i += 256) {
            int r = i >> 4, c = (i & 15) << 2;
            float4 v = *(const float4*)(Kp + (size_t)(m0 + r) * DH + c);
            Ks[r][c] = v.x; Ks[r][c+1] = v.y; Ks[r][c+2] = v.z; Ks[r][c+3] = v.w;
        }
        __syncthreads();

        #pragma unroll
        for (int m = 0; m < 32; m++) {
            float pr[4], kr[4];
            #pragma unroll
            for (int i = 0; i < 4; i++) pr[i] = Ps[tr + i][m];
            #pragma unroll
            for (int j = 0; j < 4; j++) kr[j] = Ks[m][tc + j];
            #pragma unroll
            for (int i = 0; i < 4; i++)
                #pragma unroll
                for (int j = 0; j < 4; j++)
                    acc[i][j] = fmaf(pr[i], kr[j], acc[i][j]);
        }
        __syncthreads();
    }

    #pragma unroll
    for (int i = 0; i < 4; i++)
        #pragma unroll
        for (int j = 0; j < 4; j++)
            Ch[((size_t)z * LSEQ + lt * 64 + tr + i) * DH + tc + j] = acc[i][j];
}

// ---------------- layernorm over rows of 768 ----------------
__global__ __launch_bounds__(256) void layernorm_rows_k(
    const float* __restrict__ X, const float* __restrict__ g,
    const float* __restrict__ be, float* __restrict__ Y)
{
    const int row = blockIdx.x;
    const float* x = X + (size_t)row * HID;
    float* y = Y + (size_t)row * HID;
    const int tid = threadIdx.x;
    __shared__ float shs[8], shss[8];

    float s = 0.0f, ss = 0.0f;
    for (int c = tid; c < HID; c += 256) {
        float v = x[c];
        s += v;
        ss = fmaf(v, v, ss);
    }
    #pragma unroll
    for (int o = 16; o; o >>= 1) {
        s  += __shfl_xor_sync(0xffffffffu, s, o);
        ss += __shfl_xor_sync(0xffffffffu, ss, o);
    }
    if ((tid & 31) == 0) { shs[tid >> 5] = s; shss[tid >> 5] = ss; }
    __syncthreads();
    if (tid == 0) {
        float a = 0.0f, b = 0.0f;
        #pragma unroll
        for (int i = 0; i < 8; i++) { a += shs[i]; b += shss[i]; }
        shs[0] = a; shss[0] = b;
    }
    __syncthreads();
    const float mu  = shs[0]  * (1.0f / HID);
    const float var = shss[0] * (1.0f / HID) - mu * mu;
    const float inv = rsqrtf(var + 1e-5f);
    for (int c = tid; c < HID; c += 256)
        y[c] = (x[c] - mu) * inv * g[c] + be[c];
}

// ---------------- host launch ----------------
extern "C" void kernel_launch(void* const* d_in, const int* in_sizes, int n_in,
                              void* d_out, int out_size)
{
    const float* x   = (const float*)d_in[0];
    const float* Wq  = (const float*)d_in[1];
    const float* Wk  = (const float*)d_in[2];
    // d_in[3] = Wv: unused (ctx contracts with K in the reference)
    const float* Wo  = (const float*)d_in[4];
    const float* W1  = (const float*)d_in[5];
    const float* b1  = (const float*)d_in[6];
    const float* W2  = (const float*)d_in[7];
    const float* b2  = (const float*)d_in[8];
    const float* g1  = (const float*)d_in[9];
    const float* be1 = (const float*)d_in[10];
    const float* g2  = (const float*)d_in[11];
    const float* be2 = (const float*)d_in[12];
    float* out = (float*)d_out;

    float *Q, *K, *Qh, *Kh, *S, *Ch, *Ctx, *y, *x1, *Hf, *y2;
    cudaGetSymbolAddress((void**)&Q,  g_Q);
    cudaGetSymbolAddress((void**)&K,  g_K);
    cudaGetSymbolAddress((void**)&Qh, g_Qh);
    cudaGetSymbolAddress((void**)&Kh, g_Kh);
    cudaGetSymbolAddress((void**)&S,  g_S);
    cudaGetSymbolAddress((void**)&Ch, g_Ch);
    cudaGetSymbolAddress((void**)&Ctx,g_Ctx);
    cudaGetSymbolAddress((void**)&y,  g_y);
    cudaGetSymbolAddress((void**)&x1, g_x1);
    cudaGetSymbolAddress((void**)&Hf, g_Hf);
    cudaGetSymbolAddress((void**)&y2, g_y2);

    const int nperm = MROWS * HID;

    // Q = x @ Wq ; K = x @ Wk
    sgemm128<EPI_NONE><<<dim3(HID / 128, MROWS / 128), 256>>>(x, Wq, Q, nullptr, nullptr, MROWS, HID, HID);
    sgemm128<EPI_NONE><<<dim3(HID / 128, MROWS / 128), 256>>>(x, Wk, K, nullptr, nullptr, MROWS, HID, HID);

    // permute to head-major [b*12+n][l][d]  (h = d*12 + n)
    to_head_k<<<(nperm + 255) / 256, 256>>>(Q, Qh);
    to_head_k<<<(nperm + 255) / 256, 256>>>(K, Kh);

    // S = (Qh Kh^T) / 8 ; softmax over keys ; Ch = P @ Kh (K used as V per reference)
    attn_scores_k<<<dim3(LSEQ / 64, LSEQ / 64, NHEADS_TOT), 256>>>(Qh, Kh, S);
    softmax_rows_k<<<NHEADS_TOT * LSEQ, 256>>>(S);
    attn_ctx_k<<<dim3(LSEQ / 64, NHEADS_TOT), 256>>>(S, Kh, Ch);
    from_head_k<<<(nperm + 255) / 256, 256>>>(Ch, Ctx);

    // y = ctx @ Wo + x ; x1 = LN(y)
    sgemm128<EPI_RES><<<dim3(HID / 128, MROWS / 128), 256>>>(Ctx, Wo, y, nullptr, x, MROWS, HID, HID);
    layernorm_rows_k<<<MROWS, 256>>>(y, g1, be1, x1);

    // Hf = gelu(x1 @ W1 + b1) ; y2 = Hf @ W2 + b2 + x1 ; out = LN(y2)
    sgemm128<EPI_BIAS_GELU><<<dim3(MLPD / 128, MROWS / 128), 256>>>(x1, W1, Hf, b1, nullptr, MROWS, MLPD, HID);
    sgemm128<EPI_BIAS_RES><<<dim3(HID / 128, MROWS / 128), 256>>>(Hf, W2, y2, b2, x1, MROWS, HID, MLPD);
    layernorm_rows_k<<<MROWS, 256>>>(y2, g2, be2, out);
}

// round 3
// speedup vs baseline: 1.9061x; 1.9061x over previous
#include <cuda_runtime.h>
#include <math.h>
#include <stdint.h>

#define BATCH 8
#define LSEQ  1024
#define HID   768
#define NH    12
#define DH    64
#define MLPD  3072
#define MROWS (BATCH*LSEQ)    // 8192
#define NHEADS_TOT (BATCH*NH) // 96

// ---------------- static scratch (no allocations allowed) ----------------
__device__ float g_Q  [MROWS*HID];
__device__ float g_K  [MROWS*HID];
__device__ float g_Qh [MROWS*HID];
__device__ float g_Kh [MROWS*HID];
__device__ float g_S  [(size_t)NHEADS_TOT*LSEQ*LSEQ];   // 402 MB
__device__ float g_Ch [MROWS*HID];
__device__ float g_Ctx[MROWS*HID];
__device__ float g_y  [MROWS*HID];
__device__ float g_x1 [MROWS*HID];
__device__ float g_Hf [(size_t)MROWS*MLPD];
__device__ float g_y2 [MROWS*HID];

// ---------------- helpers ----------------
__device__ __forceinline__ float gelu_f(float v) {
    return 0.5f * v * (1.0f + erff(v * 0.7071067811865475f));
}

__device__ __forceinline__ uint32_t f2tf32(float f) {
    uint32_t u;
    asm("cvt.rna.tf32.f32 %0, %1;" : "=r"(u) : "f"(f));
    return u;
}

__device__ __forceinline__ void mma_tf32(float* d, const uint32_t* a, const uint32_t* b) {
    asm volatile(
        "mma.sync.aligned.m16n8k8.row.col.f32.tf32.tf32.f32 "
        "{%0,%1,%2,%3}, {%4,%5,%6,%7}, {%8,%9}, {%0,%1,%2,%3};\n"
        : "+f"(d[0]), "+f"(d[1]), "+f"(d[2]), "+f"(d[3])
        : "r"(a[0]), "r"(a[1]), "r"(a[2]), "r"(a[3]),
          "r"(b[0]), "r"(b[1]));
}

enum { EPI_NONE = 0, EPI_RES = 1, EPI_BIAS_GELU = 2, EPI_BIAS_RES = 3 };

// ---------------- TF32 tensor-core GEMM: C = A(MxK) @ B(KxN) ----------------
// 128x128 CTA tile, BK=16, 8 warps (2x4), each warp 64x32 via m16n8k8 mma.
// A,B rounded to tf32 at smem store; fp32 accumulate.
#define AS_STR 20
#define BS_STR 136

template<int EPI>
__global__ __launch_bounds__(256) void gemm_tc(
    const float* __restrict__ A, const float* __restrict__ B, float* __restrict__ C,
    const float* __restrict__ bias, const float* __restrict__ res,
    int M, int N, int K)
{
    __shared__ uint32_t As[2][128][AS_STR];
    __shared__ uint32_t Bs[2][16][BS_STR];

    const int tid  = threadIdx.x;
    const int lane = tid & 31;
    const int warp = tid >> 5;
    const int grp  = lane >> 2;   // 0..7
    const int tg   = lane & 3;    // 0..3
    const int wm   = (warp >> 2) * 64;   // warp M offset in tile
    const int wn   = (warp & 3) * 32;    // warp N offset in tile
    const int bx   = blockIdx.x;
    const int by   = blockIdx.y;

    float acc[4][4][4];
    #pragma unroll
    for (int i = 0; i < 4; i++)
        #pragma unroll
        for (int j = 0; j < 4; j++)
            #pragma unroll
            for (int r = 0; r < 4; r++) acc[i][j][r] = 0.0f;

    const int ntiles = K >> 4;
    float4 areg[2], breg[2];

    // ---- prologue: load tile 0 ----
    #pragma unroll
    for (int i = 0; i < 2; i++) {
        int f = tid + 256 * i;
        areg[i] = *(const float4*)(A + (size_t)(by * 128 + (f >> 2)) * K + (f & 3) * 4);
        breg[i] = *(const float4*)(B + (size_t)(f >> 5) * N + bx * 128 + (f & 31) * 4);
    }
    #pragma unroll
    for (int i = 0; i < 2; i++) {
        int f = tid + 256 * i;
        int ar = f >> 2, ac = (f & 3) * 4;
        As[0][ar][ac + 0] = f2tf32(areg[i].x);
        As[0][ar][ac + 1] = f2tf32(areg[i].y);
        As[0][ar][ac + 2] = f2tf32(areg[i].z);
        As[0][ar][ac + 3] = f2tf32(areg[i].w);
        int br = f >> 5, bc = (f & 31) * 4;
        uint4 pb;
        pb.x = f2tf32(breg[i].x); pb.y = f2tf32(breg[i].y);
        pb.z = f2tf32(breg[i].z); pb.w = f2tf32(breg[i].w);
        *(uint4*)&Bs[0][br][bc] = pb;
    }
    __syncthreads();

    int cur = 0;
    for (int t = 0; t < ntiles; t++) {
        // ---- async-ish: issue next tile's global loads first ----
        if (t + 1 < ntiles) {
            const int k0 = (t + 1) * 16;
            #pragma unroll
            for (int i = 0; i < 2; i++) {
                int f = tid + 256 * i;
                areg[i] = *(const float4*)(A + (size_t)(by * 128 + (f >> 2)) * K + k0 + (f & 3) * 4);
                breg[i] = *(const float4*)(B + (size_t)(k0 + (f >> 5)) * N + bx * 128 + (f & 31) * 4);
            }
        }

        // ---- compute on current buffer ----
        #pragma unroll
        for (int kk = 0; kk < 16; kk += 8) {
            uint32_t a[4][4], b[4][2];
            #pragma unroll
            for (int mt = 0; mt < 4; mt++) {
                const int r = wm + mt * 16 + grp;
                a[mt][0] = As[cur][r    ][kk + tg];
                a[mt][1] = As[cur][r + 8][kk + tg];
                a[mt][2] = As[cur][r    ][kk + tg + 4];
                a[mt][3] = As[cur][r + 8][kk + tg + 4];
            }
            #pragma unroll
            for (int nt = 0; nt < 4; nt++) {
                const int c = wn + nt * 8 + grp;
                b[nt][0] = Bs[cur][kk + tg    ][c];
                b[nt][1] = Bs[cur][kk + tg + 4][c];
            }
            #pragma unroll
            for (int mt = 0; mt < 4; mt++)
                #pragma unroll
                for (int nt = 0; nt < 4; nt++)
                    mma_tf32(acc[mt][nt], a[mt], b[nt]);
        }

        // ---- store next tile into other buffer ----
        if (t + 1 < ntiles) {
            const int nxt = cur ^ 1;
            #pragma unroll
            for (int i = 0; i < 2; i++) {
                int f = tid + 256 * i;
                int ar = f >> 2, ac = (f & 3) * 4;
                As[nxt][ar][ac + 0] = f2tf32(areg[i].x);
                As[nxt][ar][ac + 1] = f2tf32(areg[i].y);
                As[nxt][ar][ac + 2] = f2tf32(areg[i].z);
                As[nxt][ar][ac + 3] = f2tf32(areg[i].w);
                int br = f >> 5, bc = (f & 31) * 4;
                uint4 pb;
                pb.x = f2tf32(breg[i].x); pb.y = f2tf32(breg[i].y);
                pb.z = f2tf32(breg[i].z); pb.w = f2tf32(breg[i].w);
                *(uint4*)&Bs[nxt][br][bc] = pb;
            }
        }
        __syncthreads();
        cur ^= 1;
    }

    // ---- epilogue ----
    #pragma unroll
    for (int mt = 0; mt < 4; mt++) {
        #pragma unroll
        for (int nt = 0; nt < 4; nt++) {
            const int r0 = by * 128 + wm + mt * 16 + grp;
            const int c0 = bx * 128 + wn + nt * 8 + tg * 2;
            float v0 = acc[mt][nt][0], v1 = acc[mt][nt][1];
            float v2 = acc[mt][nt][2], v3 = acc[mt][nt][3];
            if (EPI == EPI_RES) {
                const float2 r0v = *(const float2*)&res[(size_t)r0 * N + c0];
                const float2 r1v = *(const float2*)&res[(size_t)(r0 + 8) * N + c0];
                v0 += r0v.x; v1 += r0v.y; v2 += r1v.x; v3 += r1v.y;
            }
            if (EPI == EPI_BIAS_GELU) {
                const float2 bv = *(const float2*)&bias[c0];
                v0 = gelu_f(v0 + bv.x); v1 = gelu_f(v1 + bv.y);
                v2 = gelu_f(v2 + bv.x); v3 = gelu_f(v3 + bv.y);
            }
            if (EPI == EPI_BIAS_RES) {
                const float2 bv = *(const float2*)&bias[c0];
                const float2 r0v = *(const float2*)&res[(size_t)r0 * N + c0];
                const float2 r1v = *(const float2*)&res[(size_t)(r0 + 8) * N + c0];
                v0 += bv.x + r0v.x; v1 += bv.y + r0v.y;
                v2 += bv.x + r1v.x; v3 += bv.y + r1v.y;
            }
            float2 w0 = {v0, v1}, w1 = {v2, v3};
            *(float2*)&C[(size_t)r0 * N + c0] = w0;
            *(float2*)&C[(size_t)(r0 + 8) * N + c0] = w1;
        }
    }
}

// ---------------- permutes: interleaved (h = d*12 + n) <-> head-major ----------------
__global__ void to_head_k(const float* __restrict__ X, float* __restrict__ Xh) {
    int idx = blockIdx.x * blockDim.x + threadIdx.x;
    if (idx >= MROWS * HID) return;
    int d = idx & 63;
    int l = (idx >> 6) & 1023;
    int z = idx >> 16;
    int n = z % NH, b = z / NH;
    Xh[idx] = X[(size_t)(b * LSEQ + l) * HID + d * NH + n];
}

__global__ void from_head_k(const float* __restrict__ Xh, float* __restrict__ X) {
    int idx = blockIdx.x * blockDim.x + threadIdx.x;
    if (idx >= MROWS * HID) return;
    int h = idx % HID;
    int row = idx / HID;
    int l = row & 1023, b = row >> 10;
    int d = h / NH, n = h % NH;
    X[idx] = Xh[((size_t)(b * NH + n) * LSEQ + l) * DH + d];
}

// ---------------- attention scores ----------------
__global__ __launch_bounds__(256) void attn_scores_k(
    const float* __restrict__ Qh, const float* __restrict__ Kh, float* __restrict__ S)
{
    const int z = blockIdx.z;
    const int lt = blockIdx.y, mt = blockIdx.x;
    const float* Q  = Qh + ((size_t)z * LSEQ + lt * 64) * DH;
    const float* Kp = Kh + ((size_t)z * LSEQ + mt * 64) * DH;

    __shared__ float Qs[64][DH + 1];
    __shared__ float Ks[64][DH + 1];
    const int tid = threadIdx.x;

    for (int i = tid; i < 64 * 16; i += 256) {
        int r = i >> 4, c = (i & 15) << 2;
        float4 q4 = *(const float4*)(Q + r * DH + c);
        Qs[r][c] = q4.x; Qs[r][c+1] = q4.y; Qs[r][c+2] = q4.z; Qs[r][c+3] = q4.w;
        float4 k4 = *(const float4*)(Kp + r * DH + c);
        Ks[r][c] = k4.x; Ks[r][c+1] = k4.y; Ks[r][c+2] = k4.z; Ks[r][c+3] = k4.w;
    }
    __syncthreads();

    const int tr = (tid >> 4) << 2;
    const int tc = (tid & 15) << 2;
    float acc[4][4];
    #pragma unroll
    for (int i = 0; i < 4; i++)
        #pragma unroll
        for (int j = 0; j < 4; j++) acc[i][j] = 0.0f;

    #pragma unroll 8
    for (int d = 0; d < DH; d++) {
        float q[4], k[4];
        #pragma unroll
        for (int i = 0; i < 4; i++) q[i] = Qs[tr + i][d];
        #pragma unroll
        for (int j = 0; j < 4; j++) k[j] = Ks[tc + j][d];
        #pragma unroll
        for (int i = 0; i < 4; i++)
            #pragma unroll
            for (int j = 0; j < 4; j++)
                acc[i][j] = fmaf(q[i], k[j], acc[i][j]);
    }

    float* Sp = S + (size_t)z * LSEQ * LSEQ;
    #pragma unroll
    for (int i = 0; i < 4; i++)
        #pragma unroll
        for (int j = 0; j < 4; j++)
            Sp[(size_t)(lt * 64 + tr + i) * LSEQ + (mt * 64 + tc + j)] = acc[i][j] * 0.125f;
}

// ---------------- row softmax over 1024 columns ----------------
__global__ __launch_bounds__(256) void softmax_rows_k(float* __restrict__ S) {
    float* p = S + (size_t)blockIdx.x * LSEQ;
    const int tid = threadIdx.x;
    __shared__ float sh[8];

    float m = -3.0e38f;
    for (int c = tid; c < LSEQ; c += 256) m = fmaxf(m, p[c]);
    #pragma unroll
    for (int o = 16; o; o >>= 1) m = fmaxf(m, __shfl_xor_sync(0xffffffffu, m, o));
    if ((tid & 31) == 0) sh[tid >> 5] = m;
    __syncthreads();
    if (tid == 0) {
        float v = sh[0];
        #pragma unroll
        for (int i = 1; i < 8; i++) v = fmaxf(v, sh[i]);
        sh[0] = v;
    }
    __syncthreads();
    m = sh[0];
    __syncthreads();

    float s = 0.0f;
    for (int c = tid; c < LSEQ; c += 256) {
        float e = expf(p[c] - m);
        p[c] = e;
        s += e;
    }
    #pragma unroll
    for (int o = 16; o; o >>= 1) s += __shfl_xor_sync(0xffffffffu, s, o);
    if ((tid & 31) == 0) sh[tid >> 5] = s;
    __syncthreads();
    if (tid == 0) {
        float v = 0.0f;
        #pragma unroll
        for (int i = 0; i < 8; i++) v += sh[i];
        sh[0] = v;
    }
    __syncthreads();
    const float inv = 1.0f / sh[0];
    for (int c = tid; c < LSEQ; c += 256) p[c] *= inv;
}

// ---------------- ctx: Ch[z][l][d] = sum_m P[z][l][m] * Kh[z][m][d] ----------------
__global__ __launch_bounds__(256) void attn_ctx_k(
    const float* __restrict__ S, const float* __restrict__ Kh, float* __restrict__ Ch)
{
    const int z = blockIdx.y;
    const int lt = blockIdx.x;
    const float* Sp = S + (size_t)z * LSEQ * LSEQ + (size_t)(lt * 64) * LSEQ;
    const float* Kp = Kh + (size_t)z * LSEQ * DH;

    __shared__ float Ps[64][33];
    __shared__ float Ks[32][DH + 1];
    const int tid = threadIdx.x;
    const int tr = (tid >> 4) << 2;
    const int tc = (tid & 15) << 2;

    float acc[4][4];
    #pragma unroll
    for (int i = 0; i < 4; i++)
        #pragma unroll
        for (int j = 0; j < 4; j++) acc[i][j] = 0.0f;

    for (int m0 = 0; m0 < LSEQ; m0 += 32) {
        for (int i = tid; i < 64 * 8; i += 256) {
            int r = i >> 3, c = (i & 7) << 2;
            float4 v = *(const float4*)(Sp + (size_t)r * LSEQ + m0 + c);
            Ps[r][c] = v.x; Ps[r][c+1] = v.y; Ps[r][c+2] = v.z; Ps[r][c+3] = v.w;
        }
        for (int i = tid; i < 32 * 16; i += 256) {
            int r = i >> 4, c = (i & 15) << 2;
            float4 v = *(const float4*)(Kp + (size_t)(m0 + r) * DH + c);
            Ks[r][c] = v.x; Ks[r][c+1] = v.y; Ks[r][c+2] = v.z; Ks[r][c+3] = v.w;
        }
        __syncthreads();

        #pragma unroll
        for (int m = 0; m < 32; m++) {
            float pr[4], kr[4];
            #pragma unroll
            for (int i = 0; i < 4; i++) pr[i] = Ps[tr + i][m];
            #pragma unroll
            for (int j = 0; j < 4; j++) kr[j] = Ks[m][tc + j];
            #pragma unroll
            for (int i = 0; i < 4; i++)
                #pragma unroll
                for (int j = 0; j < 4; j++)
                    acc[i][j] = fmaf(pr[i], kr[j], acc[i][j]);
        }
        __syncthreads();
    }

    #pragma unroll
    for (int i = 0; i < 4; i++)
        #pragma unroll
        for (int j = 0; j < 4; j++)
            Ch[((size_t)z * LSEQ + lt * 64 + tr + i) * DH + tc + j] = acc[i][j];
}

// ---------------- layernorm over rows of 768 ----------------
__global__ __launch_bounds__(256) void layernorm_rows_k(
    const float* __restrict__ X, const float* __restrict__ g,
    const float* __restrict__ be, float* __restrict__ Y)
{
    const int row = blockIdx.x;
    const float* x = X + (size_t)row * HID;
    float* y = Y + (size_t)row * HID;
    const int tid = threadIdx.x;
    __shared__ float shs[8], shss[8];

    float s = 0.0f, ss = 0.0f;
    for (int c = tid; c < HID; c += 256) {
        float v = x[c];
        s += v;
        ss = fmaf(v, v, ss);
    }
    #pragma unroll
    for (int o = 16; o; o >>= 1) {
        s  += __shfl_xor_sync(0xffffffffu, s, o);
        ss += __shfl_xor_sync(0xffffffffu, ss, o);
    }
    if ((tid & 31) == 0) { shs[tid >> 5] = s; shss[tid >> 5] = ss; }
    __syncthreads();
    if (tid == 0) {
        float a = 0.0f, b = 0.0f;
        #pragma unroll
        for (int i = 0; i < 8; i++) { a += shs[i]; b += shss[i]; }
        shs[0] = a; shss[0] = b;
    }
    __syncthreads();
    const float mu  = shs[0]  * (1.0f / HID);
    const float var = shss[0] * (1.0f / HID) - mu * mu;
    const float inv = rsqrtf(var + 1e-5f);
    for (int c = tid; c < HID; c += 256)
        y[c] = (x[c] - mu) * inv * g[c] + be[c];
}

// ---------------- host launch ----------------
extern "C" void kernel_launch(void* const* d_in, const int* in_sizes, int n_in,
                              void* d_out, int out_size)
{
    const float* x   = (const float*)d_in[0];
    const float* Wq  = (const float*)d_in[1];
    const float* Wk  = (const float*)d_in[2];
    // d_in[3] = Wv: unused (ctx contracts with K in the reference)
    const float* Wo  = (const float*)d_in[4];
    const float* W1  = (const float*)d_in[5];
    const float* b1  = (const float*)d_in[6];
    const float* W2  = (const float*)d_in[7];
    const float* b2  = (const float*)d_in[8];
    const float* g1  = (const float*)d_in[9];
    const float* be1 = (const float*)d_in[10];
    const float* g2  = (const float*)d_in[11];
    const float* be2 = (const float*)d_in[12];
    float* out = (float*)d_out;

    float *Q, *K, *Qh, *Kh, *S, *Ch, *Ctx, *y, *x1, *Hf, *y2;
    cudaGetSymbolAddress((void**)&Q,  g_Q);
    cudaGetSymbolAddress((void**)&K,  g_K);
    cudaGetSymbolAddress((void**)&Qh, g_Qh);
    cudaGetSymbolAddress((void**)&Kh, g_Kh);
    cudaGetSymbolAddress((void**)&S,  g_S);
    cudaGetSymbolAddress((void**)&Ch, g_Ch);
    cudaGetSymbolAddress((void**)&Ctx,g_Ctx);
    cudaGetSymbolAddress((void**)&y,  g_y);
    cudaGetSymbolAddress((void**)&x1, g_x1);
    cudaGetSymbolAddress((void**)&Hf, g_Hf);
    cudaGetSymbolAddress((void**)&y2, g_y2);

    const int nperm = MROWS * HID;

    // Q = x @ Wq ; K = x @ Wk   (tensor cores, tf32)
    gemm_tc<EPI_NONE><<<dim3(HID / 128, MROWS / 128), 256>>>(x, Wq, Q, nullptr, nullptr, MROWS, HID, HID);
    gemm_tc<EPI_NONE><<<dim3(HID / 128, MROWS / 128), 256>>>(x, Wk, K, nullptr, nullptr, MROWS, HID, HID);

    // permute to head-major [b*12+n][l][d]  (h = d*12 + n)
    to_head_k<<<(nperm + 255) / 256, 256>>>(Q, Qh);
    to_head_k<<<(nperm + 255) / 256, 256>>>(K, Kh);

    // S = (Qh Kh^T) / 8 ; softmax over keys ; Ch = P @ Kh (K used as V per reference)
    attn_scores_k<<<dim3(LSEQ / 64, LSEQ / 64, NHEADS_TOT), 256>>>(Qh, Kh, S);
    softmax_rows_k<<<NHEADS_TOT * LSEQ, 256>>>(S);
    attn_ctx_k<<<dim3(LSEQ / 64, NHEADS_TOT), 256>>>(S, Kh, Ch);
    from_head_k<<<(nperm + 255) / 256, 256>>>(Ch, Ctx);

    // y = ctx @ Wo + x ; x1 = LN(y)
    gemm_tc<EPI_RES><<<dim3(HID / 128, MROWS / 128), 256>>>(Ctx, Wo, y, nullptr, x, MROWS, HID, HID);
    layernorm_rows_k<<<MROWS, 256>>>(y, g1, be1, x1);

    // Hf = gelu(x1 @ W1 + b1) ; y2 = Hf @ W2 + b2 + x1 ; out = LN(y2)
    gemm_tc<EPI_BIAS_GELU><<<dim3(MLPD / 128, MROWS / 128), 256>>>(x1, W1, Hf, b1, nullptr, MROWS, MLPD, HID);
    gemm_tc<EPI_BIAS_RES><<<dim3(HID / 128, MROWS / 128), 256>>>(Hf, W2, y2, b2, x1, MROWS, HID, MLPD);
    layernorm_rows_k<<<MROWS, 256>>>(y2, g2, be2, out);
}

// round 4
// speedup vs baseline: 3.4234x; 1.7960x over previous
#include <cuda_runtime.h>
#include <math.h>
#include <stdint.h>

#define BATCH 8
#define LSEQ  1024
#define HID   768
#define NH    12
#define DH    64
#define MLPD  3072
#define MROWS (BATCH*LSEQ)    // 8192
#define NHEADS_TOT (BATCH*NH) // 96

// ---------------- static scratch ----------------
__device__ float g_Q  [MROWS*HID];
__device__ float g_K  [MROWS*HID];
__device__ float g_Qh [MROWS*HID];
__device__ float g_Kh [MROWS*HID];
__device__ float g_Ch [MROWS*HID];
__device__ float g_Ctx[MROWS*HID];
__device__ float g_y  [MROWS*HID];
__device__ float g_x1 [MROWS*HID];
__device__ float g_Hf [(size_t)MROWS*MLPD];
__device__ float g_y2 [MROWS*HID];

// ---------------- helpers ----------------
__device__ __forceinline__ float gelu_f(float v) {
    return 0.5f * v * (1.0f + erff(v * 0.7071067811865475f));
}

__device__ __forceinline__ uint32_t f2tf32(float f) {
    uint32_t u;
    asm("cvt.rna.tf32.f32 %0, %1;" : "=r"(u) : "f"(f));
    return u;
}

__device__ __forceinline__ void mma_tf32(float* d, const uint32_t* a, const uint32_t* b) {
    asm volatile(
        "mma.sync.aligned.m16n8k8.row.col.f32.tf32.tf32.f32 "
        "{%0,%1,%2,%3}, {%4,%5,%6,%7}, {%8,%9}, {%0,%1,%2,%3};\n"
        : "+f"(d[0]), "+f"(d[1]), "+f"(d[2]), "+f"(d[3])
        : "r"(a[0]), "r"(a[1]), "r"(a[2]), "r"(a[3]),
          "r"(b[0]), "r"(b[1]));
}

enum { EPI_NONE = 0, EPI_RES = 1, EPI_BIAS_GELU = 2, EPI_BIAS_RES = 3 };

// ---------------- TF32 tensor-core GEMM: C = A(MxK) @ B(KxN) ----------------
#define AS_STR 20
#define BS_STR 136

template<int EPI>
__global__ __launch_bounds__(256) void gemm_tc(
    const float* __restrict__ A, const float* __restrict__ B, float* __restrict__ C,
    const float* __restrict__ bias, const float* __restrict__ res,
    int M, int N, int K)
{
    __shared__ uint32_t As[2][128][AS_STR];
    __shared__ uint32_t Bs[2][16][BS_STR];

    const int tid  = threadIdx.x;
    const int lane = tid & 31;
    const int warp = tid >> 5;
    const int grp  = lane >> 2;
    const int tg   = lane & 3;
    const int wm   = (warp >> 2) * 64;
    const int wn   = (warp & 3) * 32;
    const int bx   = blockIdx.x;
    const int by   = blockIdx.y;

    float acc[4][4][4];
    #pragma unroll
    for (int i = 0; i < 4; i++)
        #pragma unroll
        for (int j = 0; j < 4; j++)
            #pragma unroll
            for (int r = 0; r < 4; r++) acc[i][j][r] = 0.0f;

    const int ntiles = K >> 4;
    float4 areg[2], breg[2];

    #pragma unroll
    for (int i = 0; i < 2; i++) {
        int f = tid + 256 * i;
        areg[i] = *(const float4*)(A + (size_t)(by * 128 + (f >> 2)) * K + (f & 3) * 4);
        breg[i] = *(const float4*)(B + (size_t)(f >> 5) * N + bx * 128 + (f & 31) * 4);
    }
    #pragma unroll
    for (int i = 0; i < 2; i++) {
        int f = tid + 256 * i;
        int ar = f >> 2, ac = (f & 3) * 4;
        As[0][ar][ac + 0] = f2tf32(areg[i].x);
        As[0][ar][ac + 1] = f2tf32(areg[i].y);
        As[0][ar][ac + 2] = f2tf32(areg[i].z);
        As[0][ar][ac + 3] = f2tf32(areg[i].w);
        int br = f >> 5, bc = (f & 31) * 4;
        uint4 pb;
        pb.x = f2tf32(breg[i].x); pb.y = f2tf32(breg[i].y);
        pb.z = f2tf32(breg[i].z); pb.w = f2tf32(breg[i].w);
        *(uint4*)&Bs[0][br][bc] = pb;
    }
    __syncthreads();

    int cur = 0;
    for (int t = 0; t < ntiles; t++) {
        if (t + 1 < ntiles) {
            const int k0 = (t + 1) * 16;
            #pragma unroll
            for (int i = 0; i < 2; i++) {
                int f = tid + 256 * i;
                areg[i] = *(const float4*)(A + (size_t)(by * 128 + (f >> 2)) * K + k0 + (f & 3) * 4);
                breg[i] = *(const float4*)(B + (size_t)(k0 + (f >> 5)) * N + bx * 128 + (f & 31) * 4);
            }
        }

        #pragma unroll
        for (int kk = 0; kk < 16; kk += 8) {
            uint32_t a[4][4], b[4][2];
            #pragma unroll
            for (int mt = 0; mt < 4; mt++) {
                const int r = wm + mt * 16 + grp;
                a[mt][0] = As[cur][r    ][kk + tg];
                a[mt][1] = As[cur][r + 8][kk + tg];
                a[mt][2] = As[cur][r    ][kk + tg + 4];
                a[mt][3] = As[cur][r + 8][kk + tg + 4];
            }
            #pragma unroll
            for (int nt = 0; nt < 4; nt++) {
                const int c = wn + nt * 8 + grp;
                b[nt][0] = Bs[cur][kk + tg    ][c];
                b[nt][1] = Bs[cur][kk + tg + 4][c];
            }
            #pragma unroll
            for (int mt = 0; mt < 4; mt++)
                #pragma unroll
                for (int nt = 0; nt < 4; nt++)
                    mma_tf32(acc[mt][nt], a[mt], b[nt]);
        }

        if (t + 1 < ntiles) {
            const int nxt = cur ^ 1;
            #pragma unroll
            for (int i = 0; i < 2; i++) {
                int f = tid + 256 * i;
                int ar = f >> 2, ac = (f & 3) * 4;
                As[nxt][ar][ac + 0] = f2tf32(areg[i].x);
                As[nxt][ar][ac + 1] = f2tf32(areg[i].y);
                As[nxt][ar][ac + 2] = f2tf32(areg[i].z);
                As[nxt][ar][ac + 3] = f2tf32(areg[i].w);
                int br = f >> 5, bc = (f & 31) * 4;
                uint4 pb;
                pb.x = f2tf32(breg[i].x); pb.y = f2tf32(breg[i].y);
                pb.z = f2tf32(breg[i].z); pb.w = f2tf32(breg[i].w);
                *(uint4*)&Bs[nxt][br][bc] = pb;
            }
        }
        __syncthreads();
        cur ^= 1;
    }

    #pragma unroll
    for (int mt = 0; mt < 4; mt++) {
        #pragma unroll
        for (int nt = 0; nt < 4; nt++) {
            const int r0 = by * 128 + wm + mt * 16 + grp;
            const int c0 = bx * 128 + wn + nt * 8 + tg * 2;
            float v0 = acc[mt][nt][0], v1 = acc[mt][nt][1];
            float v2 = acc[mt][nt][2], v3 = acc[mt][nt][3];
            if (EPI == EPI_RES) {
                const float2 r0v = *(const float2*)&res[(size_t)r0 * N + c0];
                const float2 r1v = *(const float2*)&res[(size_t)(r0 + 8) * N + c0];
                v0 += r0v.x; v1 += r0v.y; v2 += r1v.x; v3 += r1v.y;
            }
            if (EPI == EPI_BIAS_GELU) {
                const float2 bv = *(const float2*)&bias[c0];
                v0 = gelu_f(v0 + bv.x); v1 = gelu_f(v1 + bv.y);
                v2 = gelu_f(v2 + bv.x); v3 = gelu_f(v3 + bv.y);
            }
            if (EPI == EPI_BIAS_RES) {
                const float2 bv = *(const float2*)&bias[c0];
                const float2 r0v = *(const float2*)&res[(size_t)r0 * N + c0];
                const float2 r1v = *(const float2*)&res[(size_t)(r0 + 8) * N + c0];
                v0 += bv.x + r0v.x; v1 += bv.y + r0v.y;
                v2 += bv.x + r1v.x; v3 += bv.y + r1v.y;
            }
            float2 w0 = {v0, v1}, w1 = {v2, v3};
            *(float2*)&C[(size_t)r0 * N + c0] = w0;
            *(float2*)&C[(size_t)(r0 + 8) * N + c0] = w1;
        }
    }
}

// ---------------- permutes ----------------
__global__ void to_head_k(const float* __restrict__ X, float* __restrict__ Xh) {
    int idx = blockIdx.x * blockDim.x + threadIdx.x;
    if (idx >= MROWS * HID) return;
    int d = idx & 63;
    int l = (idx >> 6) & 1023;
    int z = idx >> 16;
    int n = z % NH, b = z / NH;
    Xh[idx] = X[(size_t)(b * LSEQ + l) * HID + d * NH + n];
}

__global__ void from_head_k(const float* __restrict__ Xh, float* __restrict__ X) {
    int idx = blockIdx.x * blockDim.x + threadIdx.x;
    if (idx >= MROWS * HID) return;
    int h = idx % HID;
    int row = idx / HID;
    int l = row & 1023, b = row >> 10;
    int d = h / NH, n = h % NH;
    X[idx] = Xh[((size_t)(b * NH + n) * LSEQ + l) * DH + d];
}

// ---------------- fused flash attention (TF32 mma) ----------------
// One CTA = one head x 128 query rows. Loops over 8 key tiles of 128.
// S = (Q*0.125) @ K^T via mma; streaming softmax; O += P @ K via mma.
#define QS_STR 68
#define KS_STR 68
#define PS_STR 132
#define ATTN_SMEM_WORDS (128*QS_STR + 128*KS_STR + 128*PS_STR + 128 + 128 + 512 + 512)
#define ATTN_SMEM_BYTES (ATTN_SMEM_WORDS * 4)

__global__ __launch_bounds__(256) void attn_fused(
    const float* __restrict__ Qh, const float* __restrict__ Kh, float* __restrict__ Ch)
{
    extern __shared__ uint32_t sm[];
    uint32_t* Qs = sm;                        // [128][QS_STR]
    uint32_t* Ks = Qs + 128 * QS_STR;         // [128][KS_STR]
    uint32_t* Ps = Ks + 128 * KS_STR;         // [128][PS_STR]
    float* Mrow  = (float*)(Ps + 128 * PS_STR);  // [128]
    float* Srow  = Mrow + 128;                   // [128]
    float* red1  = Srow + 128;                   // [128][4]
    float* red2  = red1 + 512;                   // [128][4]

    const int z   = blockIdx.y;
    const int l0  = blockIdx.x * 128;
    const int tid = threadIdx.x;
    const int lane = tid & 31;
    const int warp = tid >> 5;
    const int grp  = lane >> 2;
    const int tg   = lane & 3;
    const int wm   = (warp >> 2) * 64;   // S/O row offset
    const int wn   = (warp & 3) * 32;    // S col offset
    const int wn2  = (warp & 3) * 16;    // O col offset
    const int wc   = warp & 3;

    const float* Qbase = Qh + ((size_t)z * LSEQ + l0) * DH;
    const float* Kbase = Kh + (size_t)z * LSEQ * DH;

    if (tid < 128) { Mrow[tid] = -3.0e38f; Srow[tid] = 0.0f; }

    // load Q tile (scale by 1/8 folded in; exact, power of two)
    #pragma unroll
    for (int i = 0; i < 8; i++) {
        int f = tid + 256 * i;
        int r = f >> 4, c = (f & 15) * 4;
        float4 q = *(const float4*)(Qbase + r * DH + c);
        Qs[r * QS_STR + c + 0] = f2tf32(0.125f * q.x);
        Qs[r * QS_STR + c + 1] = f2tf32(0.125f * q.y);
        Qs[r * QS_STR + c + 2] = f2tf32(0.125f * q.z);
        Qs[r * QS_STR + c + 3] = f2tf32(0.125f * q.w);
    }

    float acc_o[4][2][4];
    #pragma unroll
    for (int i = 0; i < 4; i++)
        #pragma unroll
        for (int j = 0; j < 2; j++)
            #pragma unroll
            for (int r = 0; r < 4; r++) acc_o[i][j][r] = 0.0f;

    __syncthreads();

    for (int mtile = 0; mtile < LSEQ / 128; mtile++) {
        // ---- load K tile ----
        const float* Kt = Kbase + (size_t)mtile * 128 * DH;
        #pragma unroll
        for (int i = 0; i < 8; i++) {
            int f = tid + 256 * i;
            int r = f >> 4, c = (f & 15) * 4;
            float4 k4 = *(const float4*)(Kt + r * DH + c);
            Ks[r * KS_STR + c + 0] = f2tf32(k4.x);
            Ks[r * KS_STR + c + 1] = f2tf32(k4.y);
            Ks[r * KS_STR + c + 2] = f2tf32(k4.z);
            Ks[r * KS_STR + c + 3] = f2tf32(k4.w);
        }
        __syncthreads();

        // ---- S = Qs @ Ks^T ----
        float s[4][4][4];
        #pragma unroll
        for (int i = 0; i < 4; i++)
            #pragma unroll
            for (int j = 0; j < 4; j++)
                #pragma unroll
                for (int r = 0; r < 4; r++) s[i][j][r] = 0.0f;

        #pragma unroll
        for (int kk = 0; kk < DH; kk += 8) {
            uint32_t a[4][4], b[4][2];
            #pragma unroll
            for (int mt = 0; mt < 4; mt++) {
                const int r = wm + mt * 16 + grp;
                a[mt][0] = Qs[r * QS_STR + kk + tg];
                a[mt][1] = Qs[(r + 8) * QS_STR + kk + tg];
                a[mt][2] = Qs[r * QS_STR + kk + tg + 4];
                a[mt][3] = Qs[(r + 8) * QS_STR + kk + tg + 4];
            }
            #pragma unroll
            for (int nt = 0; nt < 4; nt++) {
                const int c = wn + nt * 8 + grp;
                b[nt][0] = Ks[c * KS_STR + kk + tg];      // K^T access
                b[nt][1] = Ks[c * KS_STR + kk + tg + 4];
            }
            #pragma unroll
            for (int mt = 0; mt < 4; mt++)
                #pragma unroll
                for (int nt = 0; nt < 4; nt++)
                    mma_tf32(s[mt][nt], a[mt], b[nt]);
        }

        // ---- Phase A: per-warp row max -> red1 ----
        #pragma unroll
        for (int mt = 0; mt < 4; mt++) {
            float mlo = -3.0e38f, mhi = -3.0e38f;
            #pragma unroll
            for (int nt = 0; nt < 4; nt++) {
                mlo = fmaxf(mlo, fmaxf(s[mt][nt][0], s[mt][nt][1]));
                mhi = fmaxf(mhi, fmaxf(s[mt][nt][2], s[mt][nt][3]));
            }
            mlo = fmaxf(mlo, __shfl_xor_sync(0xffffffffu, mlo, 1));
            mlo = fmaxf(mlo, __shfl_xor_sync(0xffffffffu, mlo, 2));
            mhi = fmaxf(mhi, __shfl_xor_sync(0xffffffffu, mhi, 1));
            mhi = fmaxf(mhi, __shfl_xor_sync(0xffffffffu, mhi, 2));
            if (tg == 0) {
                red1[(wm + mt * 16 + grp) * 4 + wc]     = mlo;
                red1[(wm + mt * 16 + grp + 8) * 4 + wc] = mhi;
            }
        }
        __syncthreads();

        // ---- Phase B: new max, P=exp(s-M), write Ps, row sums, rescale O ----
        float newlo[4], newhi[4], scllo[4], sclhi[4];
        #pragma unroll
        for (int mt = 0; mt < 4; mt++) {
            const int rlo = wm + mt * 16 + grp;
            const int rhi = rlo + 8;
            float4 v1 = *(const float4*)&red1[rlo * 4];
            float4 v2 = *(const float4*)&red1[rhi * 4];
            float tlo = fmaxf(fmaxf(v1.x, v1.y), fmaxf(v1.z, v1.w));
            float thi = fmaxf(fmaxf(v2.x, v2.y), fmaxf(v2.z, v2.w));
            float oldlo = Mrow[rlo], oldhi = Mrow[rhi];
            float nlo = fmaxf(oldlo, tlo), nhi = fmaxf(oldhi, thi);
            newlo[mt] = nlo; newhi[mt] = nhi;
            scllo[mt] = __expf(oldlo - nlo);
            sclhi[mt] = __expf(oldhi - nhi);

            float pslo = 0.0f, pshi = 0.0f;
            #pragma unroll
            for (int nt = 0; nt < 4; nt++) {
                const int c = wn + nt * 8 + 2 * tg;
                float p0 = __expf(s[mt][nt][0] - nlo);
                float p1 = __expf(s[mt][nt][1] - nlo);
                float p2 = __expf(s[mt][nt][2] - nhi);
                float p3 = __expf(s[mt][nt][3] - nhi);
                Ps[rlo * PS_STR + c]     = f2tf32(p0);
                Ps[rlo * PS_STR + c + 1] = f2tf32(p1);
                Ps[rhi * PS_STR + c]     = f2tf32(p2);
                Ps[rhi * PS_STR + c + 1] = f2tf32(p3);
                pslo += p0 + p1;
                pshi += p2 + p3;
            }
            pslo += __shfl_xor_sync(0xffffffffu, pslo, 1);
            pslo += __shfl_xor_sync(0xffffffffu, pslo, 2);
            pshi += __shfl_xor_sync(0xffffffffu, pshi, 1);
            pshi += __shfl_xor_sync(0xffffffffu, pshi, 2);
            if (tg == 0) {
                red2[rlo * 4 + wc] = pslo;
                red2[rhi * 4 + wc] = pshi;
            }
            #pragma unroll
            for (int nt2 = 0; nt2 < 2; nt2++) {
                acc_o[mt][nt2][0] *= scllo[mt];
                acc_o[mt][nt2][1] *= scllo[mt];
                acc_o[mt][nt2][2] *= sclhi[mt];
                acc_o[mt][nt2][3] *= sclhi[mt];
            }
        }
        __syncthreads();

        // ---- Phase C: update M/Sum (one warp column, one lane per row) ----
        if (wc == 0 && tg == 0) {
            #pragma unroll
            for (int mt = 0; mt < 4; mt++) {
                const int rlo = wm + mt * 16 + grp;
                const int rhi = rlo + 8;
                float4 w1 = *(const float4*)&red2[rlo * 4];
                float4 w2 = *(const float4*)&red2[rhi * 4];
                Srow[rlo] = Srow[rlo] * scllo[mt] + (w1.x + w1.y + w1.z + w1.w);
                Srow[rhi] = Srow[rhi] * sclhi[mt] + (w2.x + w2.y + w2.z + w2.w);
                Mrow[rlo] = newlo[mt];
                Mrow[rhi] = newhi[mt];
            }
        }

        // ---- O += P @ Ktile ----
        #pragma unroll
        for (int kk = 0; kk < 128; kk += 8) {
            uint32_t a[4][4], b[2][2];
            #pragma unroll
            for (int mt = 0; mt < 4; mt++) {
                const int r = wm + mt * 16 + grp;
                a[mt][0] = Ps[r * PS_STR + kk + tg];
                a[mt][1] = Ps[(r + 8) * PS_STR + kk + tg];
                a[mt][2] = Ps[r * PS_STR + kk + tg + 4];
                a[mt][3] = Ps[(r + 8) * PS_STR + kk + tg + 4];
            }
            #pragma unroll
            for (int nt2 = 0; nt2 < 2; nt2++) {
                const int c = wn2 + nt2 * 8 + grp;
                b[nt2][0] = Ks[(kk + tg) * KS_STR + c];
                b[nt2][1] = Ks[(kk + tg + 4) * KS_STR + c];
            }
            #pragma unroll
            for (int mt = 0; mt < 4; mt++)
                #pragma unroll
                for (int nt2 = 0; nt2 < 2; nt2++)
                    mma_tf32(acc_o[mt][nt2], a[mt], b[nt2]);
        }
        __syncthreads();
    }

    // ---- epilogue: normalize and store head-major ----
    #pragma unroll
    for (int mt = 0; mt < 4; mt++) {
        const int rlo = wm + mt * 16 + grp;
        const int rhi = rlo + 8;
        const float ilo = 1.0f / Srow[rlo];
        const float ihi = 1.0f / Srow[rhi];
        #pragma unroll
        for (int nt2 = 0; nt2 < 2; nt2++) {
            const int c = wn2 + nt2 * 8 + 2 * tg;
            float2 o0 = {acc_o[mt][nt2][0] * ilo, acc_o[mt][nt2][1] * ilo};
            float2 o1 = {acc_o[mt][nt2][2] * ihi, acc_o[mt][nt2][3] * ihi};
            *(float2*)&Ch[((size_t)z * LSEQ + l0 + rlo) * DH + c] = o0;
            *(float2*)&Ch[((size_t)z * LSEQ + l0 + rhi) * DH + c] = o1;
        }
    }
}

// ---------------- layernorm ----------------
__global__ __launch_bounds__(256) void layernorm_rows_k(
    const float* __restrict__ X, const float* __restrict__ g,
    const float* __restrict__ be, float* __restrict__ Y)
{
    const int row = blockIdx.x;
    const float* x = X + (size_t)row * HID;
    float* y = Y + (size_t)row * HID;
    const int tid = threadIdx.x;
    __shared__ float shs[8], shss[8];

    float s = 0.0f, ss = 0.0f;
    for (int c = tid; c < HID; c += 256) {
        float v = x[c];
        s += v;
        ss = fmaf(v, v, ss);
    }
    #pragma unroll
    for (int o = 16; o; o >>= 1) {
        s  += __shfl_xor_sync(0xffffffffu, s, o);
        ss += __shfl_xor_sync(0xffffffffu, ss, o);
    }
    if ((tid & 31) == 0) { shs[tid >> 5] = s; shss[tid >> 5] = ss; }
    __syncthreads();
    if (tid == 0) {
        float a = 0.0f, b = 0.0f;
        #pragma unroll
        for (int i = 0; i < 8; i++) { a += shs[i]; b += shss[i]; }
        shs[0] = a; shss[0] = b;
    }
    __syncthreads();
    const float mu  = shs[0]  * (1.0f / HID);
    const float var = shss[0] * (1.0f / HID) - mu * mu;
    const float inv = rsqrtf(var + 1e-5f);
    for (int c = tid; c < HID; c += 256)
        y[c] = (x[c] - mu) * inv * g[c] + be[c];
}

// ---------------- host launch ----------------
extern "C" void kernel_launch(void* const* d_in, const int* in_sizes, int n_in,
                              void* d_out, int out_size)
{
    const float* x   = (const float*)d_in[0];
    const float* Wq  = (const float*)d_in[1];
    const float* Wk  = (const float*)d_in[2];
    // d_in[3] = Wv: unused (ctx contracts with K in the reference)
    const float* Wo  = (const float*)d_in[4];
    const float* W1  = (const float*)d_in[5];
    const float* b1  = (const float*)d_in[6];
    const float* W2  = (const float*)d_in[7];
    const float* b2  = (const float*)d_in[8];
    const float* g1  = (const float*)d_in[9];
    const float* be1 = (const float*)d_in[10];
    const float* g2  = (const float*)d_in[11];
    const float* be2 = (const float*)d_in[12];
    float* out = (float*)d_out;

    float *Q, *K, *Qh, *Kh, *Ch, *Ctx, *y, *x1, *Hf, *y2;
    cudaGetSymbolAddress((void**)&Q,  g_Q);
    cudaGetSymbolAddress((void**)&K,  g_K);
    cudaGetSymbolAddress((void**)&Qh, g_Qh);
    cudaGetSymbolAddress((void**)&Kh, g_Kh);
    cudaGetSymbolAddress((void**)&Ch, g_Ch);
    cudaGetSymbolAddress((void**)&Ctx,g_Ctx);
    cudaGetSymbolAddress((void**)&y,  g_y);
    cudaGetSymbolAddress((void**)&x1, g_x1);
    cudaGetSymbolAddress((void**)&Hf, g_Hf);
    cudaGetSymbolAddress((void**)&y2, g_y2);

    static bool attn_attr_set = false;
    if (!attn_attr_set) {
        cudaFuncSetAttribute(attn_fused, cudaFuncAttributeMaxDynamicSharedMemorySize,
                             ATTN_SMEM_BYTES);
        attn_attr_set = true;
    }

    const int nperm = MROWS * HID;

    // Q = x @ Wq ; K = x @ Wk
    gemm_tc<EPI_NONE><<<dim3(HID / 128, MROWS / 128), 256>>>(x, Wq, Q, nullptr, nullptr, MROWS, HID, HID);
    gemm_tc<EPI_NONE><<<dim3(HID / 128, MROWS / 128), 256>>>(x, Wk, K, nullptr, nullptr, MROWS, HID, HID);

    // permute to head-major [b*12+n][l][d]  (h = d*12 + n)
    to_head_k<<<(nperm + 255) / 256, 256>>>(Q, Qh);
    to_head_k<<<(nperm + 255) / 256, 256>>>(K, Kh);

    // fused flash attention (K doubles as V per reference)
    attn_fused<<<dim3(LSEQ / 128, NHEADS_TOT), 256, ATTN_SMEM_BYTES>>>(Qh, Kh, Ch);
    from_head_k<<<(nperm + 255) / 256, 256>>>(Ch, Ctx);

    // y = ctx @ Wo + x ; x1 = LN(y)
    gemm_tc<EPI_RES><<<dim3(HID / 128, MROWS / 128), 256>>>(Ctx, Wo, y, nullptr, x, MROWS, HID, HID);
    layernorm_rows_k<<<MROWS, 256>>>(y, g1, be1, x1);

    // Hf = gelu(x1 @ W1 + b1) ; y2 = Hf @ W2 + b2 + x1 ; out = LN(y2)
    gemm_tc<EPI_BIAS_GELU><<<dim3(MLPD / 128, MROWS / 128), 256>>>(x1, W1, Hf, b1, nullptr, MROWS, MLPD, HID);
    gemm_tc<EPI_BIAS_RES><<<dim3(HID / 128, MROWS / 128), 256>>>(Hf, W2, y2, b2, x1, MROWS, HID, MLPD);
    layernorm_rows_k<<<MROWS, 256>>>(y2, g2, be2, out);
}

// round 5
// speedup vs baseline: 3.8344x; 1.1201x over previous
#include <cuda_runtime.h>
#include <math.h>
#include <stdint.h>

#define BATCH 8
#define LSEQ  1024
#define HID   768
#define NH    12
#define DH    64
#define MLPD  3072
#define MROWS (BATCH*LSEQ)    // 8192
#define NHEADS_TOT (BATCH*NH) // 96

// ---------------- static scratch ----------------
__device__ float g_QK [(size_t)MROWS*2*HID];   // merged Q|K output
__device__ float g_Qh [MROWS*HID];
__device__ float g_Kh [MROWS*HID];
__device__ float g_Ch [MROWS*HID];
__device__ float g_Ctx[MROWS*HID];
__device__ float g_y  [MROWS*HID];
__device__ float g_x1 [MROWS*HID];
__device__ float g_Hf [(size_t)MROWS*MLPD];
__device__ float g_y2 [MROWS*HID];
// rounded operands
__device__ float g_xr [MROWS*HID];
__device__ float g_Wqk[HID*2*HID];
__device__ float g_Wor[HID*HID];
__device__ float g_W1r[HID*MLPD];
__device__ float g_W2r[MLPD*HID];

// ---------------- helpers ----------------
__device__ __forceinline__ float gelu_f(float v) {
    return 0.5f * v * (1.0f + erff(v * 0.7071067811865475f));
}

__device__ __forceinline__ uint32_t f2tf32(float f) {
    uint32_t u;
    asm("cvt.rna.tf32.f32 %0, %1;" : "=r"(u) : "f"(f));
    return u;
}
__device__ __forceinline__ float rndtf(float f) { return __uint_as_float(f2tf32(f)); }

__device__ __forceinline__ void mma_tf32(float* d, const uint32_t* a, const uint32_t* b) {
    asm volatile(
        "mma.sync.aligned.m16n8k8.row.col.f32.tf32.tf32.f32 "
        "{%0,%1,%2,%3}, {%4,%5,%6,%7}, {%8,%9}, {%0,%1,%2,%3};\n"
        : "+f"(d[0]), "+f"(d[1]), "+f"(d[2]), "+f"(d[3])
        : "r"(a[0]), "r"(a[1]), "r"(a[2]), "r"(a[3]),
          "r"(b[0]), "r"(b[1]));
}

__device__ __forceinline__ void cp16(uint32_t dst, const void* src) {
    asm volatile("cp.async.cg.shared.global [%0], [%1], 16;\n" :: "r"(dst), "l"(src));
}
__device__ __forceinline__ void cp_commit() {
    asm volatile("cp.async.commit_group;\n");
}
template<int N>
__device__ __forceinline__ void cp_wait() {
    asm volatile("cp.async.wait_group %0;\n" :: "n"(N));
}

enum { EPI_NONE = 0, EPI_RES = 1, EPI_BIAS_GELU = 2, EPI_BIAS_RES = 3 };

// ---------------- TF32 tensor-core GEMM: C = A(MxK) @ B(KxN) ----------------
// 128x128 CTA tile, BK=16, 4-stage cp.async pipeline. Operands are
// pre-rounded to tf32 in gmem -> hardware truncation == RNA rounding.
#define AS_STR 20
#define BS_STR 136
#define STAGES 4
#define GEMM_SMEM_BYTES (STAGES * (128 * AS_STR + 16 * BS_STR) * 4)

template<int EPI, bool ROUND_OUT>
__global__ __launch_bounds__(256) void gemm_tc(
    const float* __restrict__ A, const float* __restrict__ B, float* __restrict__ C,
    const float* __restrict__ bias, const float* __restrict__ res,
    int M, int N, int K)
{
    extern __shared__ uint32_t dynsmem[];
    uint32_t* As = dynsmem;                            // [STAGES][128][AS_STR]
    uint32_t* Bs = dynsmem + STAGES * 128 * AS_STR;    // [STAGES][16][BS_STR]
    const uint32_t sA = (uint32_t)__cvta_generic_to_shared(As);
    const uint32_t sB = (uint32_t)__cvta_generic_to_shared(Bs);

    const int tid  = threadIdx.x;
    const int lane = tid & 31;
    const int warp = tid >> 5;
    const int grp  = lane >> 2;
    const int tg   = lane & 3;
    const int wm   = (warp >> 2) * 64;
    const int wn   = (warp & 3) * 32;
    const int bx   = blockIdx.x;
    const int by   = blockIdx.y;

    // per-thread load coords (2 chunks for A, 2 for B)
    const int ar0 = tid >> 2,  ac0 = (tid & 3) * 4;          // A chunk 0: rows 0..63
    const int ar1 = ar0 + 64;                                 // A chunk 1: rows 64..127
    const int br0 = tid >> 5,  bc0 = (tid & 31) * 4;         // B chunk 0: k rows 0..7
    const int br1 = br0 + 8;                                  // B chunk 1: k rows 8..15

    const float* Abase = A + (size_t)(by * 128) * K;
    const float* Bbase = B + bx * 128;

    float acc[4][4][4];
    #pragma unroll
    for (int i = 0; i < 4; i++)
        #pragma unroll
        for (int j = 0; j < 4; j++)
            #pragma unroll
            for (int r = 0; r < 4; r++) acc[i][j][r] = 0.0f;

    const int ntiles = K >> 4;

    auto issue = [&](int t) {
        const int st = t & (STAGES - 1);
        const int k0 = t * 16;
        const uint32_t aoff = sA + (uint32_t)(st * 128 * AS_STR) * 4;
        const uint32_t boff = sB + (uint32_t)(st * 16 * BS_STR) * 4;
        cp16(aoff + (uint32_t)(ar0 * AS_STR + ac0) * 4, Abase + (size_t)ar0 * K + k0 + ac0);
        cp16(aoff + (uint32_t)(ar1 * AS_STR + ac0) * 4, Abase + (size_t)ar1 * K + k0 + ac0);
        cp16(boff + (uint32_t)(br0 * BS_STR + bc0) * 4, Bbase + (size_t)(k0 + br0) * N + bc0);
        cp16(boff + (uint32_t)(br1 * BS_STR + bc0) * 4, Bbase + (size_t)(k0 + br1) * N + bc0);
        cp_commit();
    };

    // prologue: stages 0..2
    #pragma unroll
    for (int t = 0; t < STAGES - 1; t++) issue(t);

    for (int t = 0; t < ntiles; t++) {
        cp_wait<STAGES - 2>();
        __syncthreads();

        const int cur = t & (STAGES - 1);
        const uint32_t* Ac = As + cur * 128 * AS_STR;
        const uint32_t* Bc = Bs + cur * 16 * BS_STR;

        #pragma unroll
        for (int kk = 0; kk < 16; kk += 8) {
            uint32_t a[4][4], b[4][2];
            #pragma unroll
            for (int mt = 0; mt < 4; mt++) {
                const int r = wm + mt * 16 + grp;
                a[mt][0] = Ac[r * AS_STR + kk + tg];
                a[mt][1] = Ac[(r + 8) * AS_STR + kk + tg];
                a[mt][2] = Ac[r * AS_STR + kk + tg + 4];
                a[mt][3] = Ac[(r + 8) * AS_STR + kk + tg + 4];
            }
            #pragma unroll
            for (int nt = 0; nt < 4; nt++) {
                const int c = wn + nt * 8 + grp;
                b[nt][0] = Bc[(kk + tg) * BS_STR + c];
                b[nt][1] = Bc[(kk + tg + 4) * BS_STR + c];
            }
            #pragma unroll
            for (int mt = 0; mt < 4; mt++)
                #pragma unroll
                for (int nt = 0; nt < 4; nt++)
                    mma_tf32(acc[mt][nt], a[mt], b[nt]);
        }

        if (t + STAGES - 1 < ntiles) issue(t + STAGES - 1);
        else cp_commit();   // keep group accounting uniform
    }

    // ---- epilogue ----
    #pragma unroll
    for (int mt = 0; mt < 4; mt++) {
        #pragma unroll
        for (int nt = 0; nt < 4; nt++) {
            const int r0 = by * 128 + wm + mt * 16 + grp;
            const int c0 = bx * 128 + wn + nt * 8 + tg * 2;
            float v0 = acc[mt][nt][0], v1 = acc[mt][nt][1];
            float v2 = acc[mt][nt][2], v3 = acc[mt][nt][3];
            if (EPI == EPI_RES) {
                const float2 r0v = *(const float2*)&res[(size_t)r0 * N + c0];
                const float2 r1v = *(const float2*)&res[(size_t)(r0 + 8) * N + c0];
                v0 += r0v.x; v1 += r0v.y; v2 += r1v.x; v3 += r1v.y;
            }
            if (EPI == EPI_BIAS_GELU) {
                const float2 bv = *(const float2*)&bias[c0];
                v0 = gelu_f(v0 + bv.x); v1 = gelu_f(v1 + bv.y);
                v2 = gelu_f(v2 + bv.x); v3 = gelu_f(v3 + bv.y);
            }
            if (EPI == EPI_BIAS_RES) {
                const float2 bv = *(const float2*)&bias[c0];
                const float2 r0v = *(const float2*)&res[(size_t)r0 * N + c0];
                const float2 r1v = *(const float2*)&res[(size_t)(r0 + 8) * N + c0];
                v0 += bv.x + r0v.x; v1 += bv.y + r0v.y;
                v2 += bv.x + r1v.x; v3 += bv.y + r1v.y;
            }
            if (ROUND_OUT) {
                v0 = rndtf(v0); v1 = rndtf(v1); v2 = rndtf(v2); v3 = rndtf(v3);
            }
            float2 w0 = {v0, v1}, w1 = {v2, v3};
            *(float2*)&C[(size_t)r0 * N + c0] = w0;
            *(float2*)&C[(size_t)(r0 + 8) * N + c0] = w1;
        }
    }
}

// ---------------- operand pre-rounding kernels ----------------
__global__ void round_copy_k(const float4* __restrict__ in, float4* __restrict__ out, int n4) {
    int i = blockIdx.x * blockDim.x + threadIdx.x;
    if (i >= n4) return;
    float4 v = in[i];
    v.x = rndtf(v.x); v.y = rndtf(v.y); v.z = rndtf(v.z); v.w = rndtf(v.w);
    out[i] = v;
}

__global__ void concat_qk_k(const float* __restrict__ Wq, const float* __restrict__ Wk,
                            float* __restrict__ Wqk) {
    int i = blockIdx.x * blockDim.x + threadIdx.x;   // over HID * (HID/4)
    if (i >= HID * (HID / 4)) return;
    int k = i / (HID / 4), c = (i % (HID / 4)) * 4;
    float4 q = *(const float4*)(Wq + (size_t)k * HID + c);
    float4 kk = *(const float4*)(Wk + (size_t)k * HID + c);
    q.x = rndtf(q.x); q.y = rndtf(q.y); q.z = rndtf(q.z); q.w = rndtf(q.w);
    kk.x = rndtf(kk.x); kk.y = rndtf(kk.y); kk.z = rndtf(kk.z); kk.w = rndtf(kk.w);
    *(float4*)(Wqk + (size_t)k * (2 * HID) + c) = q;
    *(float4*)(Wqk + (size_t)k * (2 * HID) + HID + c) = kk;
}

// ---------------- permutes ----------------
// reads merged QK buffer [MROWS][2*HID], coloff selects Q (0) or K (HID)
__global__ void to_head_k(const float* __restrict__ X, float* __restrict__ Xh, int coloff) {
    int idx = blockIdx.x * blockDim.x + threadIdx.x;
    if (idx >= MROWS * HID) return;
    int d = idx & 63;
    int l = (idx >> 6) & 1023;
    int z = idx >> 16;
    int n = z % NH, b = z / NH;
    Xh[idx] = X[(size_t)(b * LSEQ + l) * (2 * HID) + coloff + d * NH + n];
}

__global__ void from_head_k(const float* __restrict__ Xh, float* __restrict__ X) {
    int idx = blockIdx.x * blockDim.x + threadIdx.x;
    if (idx >= MROWS * HID) return;
    int h = idx % HID;
    int row = idx / HID;
    int l = row & 1023, b = row >> 10;
    int d = h / NH, n = h % NH;
    X[idx] = rndtf(Xh[((size_t)(b * NH + n) * LSEQ + l) * DH + d]);   // tf32-rounded for Wo GEMM
}

// ---------------- fused flash attention (TF32 mma) ----------------
#define QS_STR 68
#define KS_STR 68
#define PS_STR 132
#define ATTN_SMEM_WORDS (128*QS_STR + 128*KS_STR + 128*PS_STR + 128 + 128 + 512 + 512)
#define ATTN_SMEM_BYTES (ATTN_SMEM_WORDS * 4)

__global__ __launch_bounds__(256) void attn_fused(
    const float* __restrict__ Qh, const float* __restrict__ Kh, float* __restrict__ Ch)
{
    extern __shared__ uint32_t sm[];
    uint32_t* Qs = sm;
    uint32_t* Ks = Qs + 128 * QS_STR;
    uint32_t* Ps = Ks + 128 * KS_STR;
    float* Mrow  = (float*)(Ps + 128 * PS_STR);
    float* Srow  = Mrow + 128;
    float* red1  = Srow + 128;
    float* red2  = red1 + 512;

    const int z   = blockIdx.y;
    const int l0  = blockIdx.x * 128;
    const int tid = threadIdx.x;
    const int lane = tid & 31;
    const int warp = tid >> 5;
    const int grp  = lane >> 2;
    const int tg   = lane & 3;
    const int wm   = (warp >> 2) * 64;
    const int wn   = (warp & 3) * 32;
    const int wn2  = (warp & 3) * 16;
    const int wc   = warp & 3;

    const float* Qbase = Qh + ((size_t)z * LSEQ + l0) * DH;
    const float* Kbase = Kh + (size_t)z * LSEQ * DH;

    if (tid < 128) { Mrow[tid] = -3.0e38f; Srow[tid] = 0.0f; }

    #pragma unroll
    for (int i = 0; i < 8; i++) {
        int f = tid + 256 * i;
        int r = f >> 4, c = (f & 15) * 4;
        float4 q = *(const float4*)(Qbase + r * DH + c);
        Qs[r * QS_STR + c + 0] = f2tf32(0.125f * q.x);
        Qs[r * QS_STR + c + 1] = f2tf32(0.125f * q.y);
        Qs[r * QS_STR + c + 2] = f2tf32(0.125f * q.z);
        Qs[r * QS_STR + c + 3] = f2tf32(0.125f * q.w);
    }

    float acc_o[4][2][4];
    #pragma unroll
    for (int i = 0; i < 4; i++)
        #pragma unroll
        for (int j = 0; j < 2; j++)
            #pragma unroll
            for (int r = 0; r < 4; r++) acc_o[i][j][r] = 0.0f;

    __syncthreads();

    for (int mtile = 0; mtile < LSEQ / 128; mtile++) {
        const float* Kt = Kbase + (size_t)mtile * 128 * DH;
        #pragma unroll
        for (int i = 0; i < 8; i++) {
            int f = tid + 256 * i;
            int r = f >> 4, c = (f & 15) * 4;
            float4 k4 = *(const float4*)(Kt + r * DH + c);
            Ks[r * KS_STR + c + 0] = f2tf32(k4.x);
            Ks[r * KS_STR + c + 1] = f2tf32(k4.y);
            Ks[r * KS_STR + c + 2] = f2tf32(k4.z);
            Ks[r * KS_STR + c + 3] = f2tf32(k4.w);
        }
        __syncthreads();

        float s[4][4][4];
        #pragma unroll
        for (int i = 0; i < 4; i++)
            #pragma unroll
            for (int j = 0; j < 4; j++)
                #pragma unroll
                for (int r = 0; r < 4; r++) s[i][j][r] = 0.0f;

        #pragma unroll
        for (int kk = 0; kk < DH; kk += 8) {
            uint32_t a[4][4], b[4][2];
            #pragma unroll
            for (int mt = 0; mt < 4; mt++) {
                const int r = wm + mt * 16 + grp;
                a[mt][0] = Qs[r * QS_STR + kk + tg];
                a[mt][1] = Qs[(r + 8) * QS_STR + kk + tg];
                a[mt][2] = Qs[r * QS_STR + kk + tg + 4];
                a[mt][3] = Qs[(r + 8) * QS_STR + kk + tg + 4];
            }
            #pragma unroll
            for (int nt = 0; nt < 4; nt++) {
                const int c = wn + nt * 8 + grp;
                b[nt][0] = Ks[c * KS_STR + kk + tg];
                b[nt][1] = Ks[c * KS_STR + kk + tg + 4];
            }
            #pragma unroll
            for (int mt = 0; mt < 4; mt++)
                #pragma unroll
                for (int nt = 0; nt < 4; nt++)
                    mma_tf32(s[mt][nt], a[mt], b[nt]);
        }

        #pragma unroll
        for (int mt = 0; mt < 4; mt++) {
            float mlo = -3.0e38f, mhi = -3.0e38f;
            #pragma unroll
            for (int nt = 0; nt < 4; nt++) {
                mlo = fmaxf(mlo, fmaxf(s[mt][nt][0], s[mt][nt][1]));
                mhi = fmaxf(mhi, fmaxf(s[mt][nt][2], s[mt][nt][3]));
            }
            mlo = fmaxf(mlo, __shfl_xor_sync(0xffffffffu, mlo, 1));
            mlo = fmaxf(mlo, __shfl_xor_sync(0xffffffffu, mlo, 2));
            mhi = fmaxf(mhi, __shfl_xor_sync(0xffffffffu, mhi, 1));
            mhi = fmaxf(mhi, __shfl_xor_sync(0xffffffffu, mhi, 2));
            if (tg == 0) {
                red1[(wm + mt * 16 + grp) * 4 + wc]     = mlo;
                red1[(wm + mt * 16 + grp + 8) * 4 + wc] = mhi;
            }
        }
        __syncthreads();

        float newlo[4], newhi[4], scllo[4], sclhi[4];
        #pragma unroll
        for (int mt = 0; mt < 4; mt++) {
            const int rlo = wm + mt * 16 + grp;
            const int rhi = rlo + 8;
            float4 v1 = *(const float4*)&red1[rlo * 4];
            float4 v2 = *(const float4*)&red1[rhi * 4];
            float tlo = fmaxf(fmaxf(v1.x, v1.y), fmaxf(v1.z, v1.w));
            float thi = fmaxf(fmaxf(v2.x, v2.y), fmaxf(v2.z, v2.w));
            float oldlo = Mrow[rlo], oldhi = Mrow[rhi];
            float nlo = fmaxf(oldlo, tlo), nhi = fmaxf(oldhi, thi);
            newlo[mt] = nlo; newhi[mt] = nhi;
            scllo[mt] = __expf(oldlo - nlo);
            sclhi[mt] = __expf(oldhi - nhi);

            float pslo = 0.0f, pshi = 0.0f;
            #pragma unroll
            for (int nt = 0; nt < 4; nt++) {
                const int c = wn + nt * 8 + 2 * tg;
                float p0 = __expf(s[mt][nt][0] - nlo);
                float p1 = __expf(s[mt][nt][1] - nlo);
                float p2 = __expf(s[mt][nt][2] - nhi);
                float p3 = __expf(s[mt][nt][3] - nhi);
                Ps[rlo * PS_STR + c]     = f2tf32(p0);
                Ps[rlo * PS_STR + c + 1] = f2tf32(p1);
                Ps[rhi * PS_STR + c]     = f2tf32(p2);
                Ps[rhi * PS_STR + c + 1] = f2tf32(p3);
                pslo += p0 + p1;
                pshi += p2 + p3;
            }
            pslo += __shfl_xor_sync(0xffffffffu, pslo, 1);
            pslo += __shfl_xor_sync(0xffffffffu, pslo, 2);
            pshi += __shfl_xor_sync(0xffffffffu, pshi, 1);
            pshi += __shfl_xor_sync(0xffffffffu, pshi, 2);
            if (tg == 0) {
                red2[rlo * 4 + wc] = pslo;
                red2[rhi * 4 + wc] = pshi;
            }
            #pragma unroll
            for (int nt2 = 0; nt2 < 2; nt2++) {
                acc_o[mt][nt2][0] *= scllo[mt];
                acc_o[mt][nt2][1] *= scllo[mt];
                acc_o[mt][nt2][2] *= sclhi[mt];
                acc_o[mt][nt2][3] *= sclhi[mt];
            }
        }
        __syncthreads();

        if (wc == 0 && tg == 0) {
            #pragma unroll
            for (int mt = 0; mt < 4; mt++) {
                const int rlo = wm + mt * 16 + grp;
                const int rhi = rlo + 8;
                float4 w1 = *(const float4*)&red2[rlo * 4];
                float4 w2 = *(const float4*)&red2[rhi * 4];
                Srow[rlo] = Srow[rlo] * scllo[mt] + (w1.x + w1.y + w1.z + w1.w);
                Srow[rhi] = Srow[rhi] * sclhi[mt] + (w2.x + w2.y + w2.z + w2.w);
                Mrow[rlo] = newlo[mt];
                Mrow[rhi] = newhi[mt];
            }
        }

        #pragma unroll
        for (int kk = 0; kk < 128; kk += 8) {
            uint32_t a[4][4], b[2][2];
            #pragma unroll
            for (int mt = 0; mt < 4; mt++) {
                const int r = wm + mt * 16 + grp;
                a[mt][0] = Ps[r * PS_STR + kk + tg];
                a[mt][1] = Ps[(r + 8) * PS_STR + kk + tg];
                a[mt][2] = Ps[r * PS_STR + kk + tg + 4];
                a[mt][3] = Ps[(r + 8) * PS_STR + kk + tg + 4];
            }
            #pragma unroll
            for (int nt2 = 0; nt2 < 2; nt2++) {
                const int c = wn2 + nt2 * 8 + grp;
                b[nt2][0] = Ks[(kk + tg) * KS_STR + c];
                b[nt2][1] = Ks[(kk + tg + 4) * KS_STR + c];
            }
            #pragma unroll
            for (int mt = 0; mt < 4; mt++)
                #pragma unroll
                for (int nt2 = 0; nt2 < 2; nt2++)
                    mma_tf32(acc_o[mt][nt2], a[mt], b[nt2]);
        }
        __syncthreads();
    }

    #pragma unroll
    for (int mt = 0; mt < 4; mt++) {
        const int rlo = wm + mt * 16 + grp;
        const int rhi = rlo + 8;
        const float ilo = 1.0f / Srow[rlo];
        const float ihi = 1.0f / Srow[rhi];
        #pragma unroll
        for (int nt2 = 0; nt2 < 2; nt2++) {
            const int c = wn2 + nt2 * 8 + 2 * tg;
            float2 o0 = {acc_o[mt][nt2][0] * ilo, acc_o[mt][nt2][1] * ilo};
            float2 o1 = {acc_o[mt][nt2][2] * ihi, acc_o[mt][nt2][3] * ihi};
            *(float2*)&Ch[((size_t)z * LSEQ + l0 + rlo) * DH + c] = o0;
            *(float2*)&Ch[((size_t)z * LSEQ + l0 + rhi) * DH + c] = o1;
        }
    }
}

// ---------------- layernorm ----------------
template<bool RND>
__global__ __launch_bounds__(256) void layernorm_rows_k(
    const float* __restrict__ X, const float* __restrict__ g,
    const float* __restrict__ be, float* __restrict__ Y)
{
    const int row = blockIdx.x;
    const float* x = X + (size_t)row * HID;
    float* y = Y + (size_t)row * HID;
    const int tid = threadIdx.x;
    __shared__ float shs[8], shss[8];

    float s = 0.0f, ss = 0.0f;
    for (int c = tid; c < HID; c += 256) {
        float v = x[c];
        s += v;
        ss = fmaf(v, v, ss);
    }
    #pragma unroll
    for (int o = 16; o; o >>= 1) {
        s  += __shfl_xor_sync(0xffffffffu, s, o);
        ss += __shfl_xor_sync(0xffffffffu, ss, o);
    }
    if ((tid & 31) == 0) { shs[tid >> 5] = s; shss[tid >> 5] = ss; }
    __syncthreads();
    if (tid == 0) {
        float a = 0.0f, b = 0.0f;
        #pragma unroll
        for (int i = 0; i < 8; i++) { a += shs[i]; b += shss[i]; }
        shs[0] = a; shss[0] = b;
    }
    __syncthreads();
    const float mu  = shs[0]  * (1.0f / HID);
    const float var = shss[0] * (1.0f / HID) - mu * mu;
    const float inv = rsqrtf(var + 1e-5f);
    for (int c = tid; c < HID; c += 256) {
        float v = (x[c] - mu) * inv * g[c] + be[c];
        y[c] = RND ? rndtf(v) : v;
    }
}

// ---------------- host launch ----------------
extern "C" void kernel_launch(void* const* d_in, const int* in_sizes, int n_in,
                              void* d_out, int out_size)
{
    const float* x   = (const float*)d_in[0];
    const float* Wq  = (const float*)d_in[1];
    const float* Wk  = (const float*)d_in[2];
    // d_in[3] = Wv: unused (ctx contracts with K in the reference)
    const float* Wo  = (const float*)d_in[4];
    const float* W1  = (const float*)d_in[5];
    const float* b1  = (const float*)d_in[6];
    const float* W2  = (const float*)d_in[7];
    const float* b2  = (const float*)d_in[8];
    const float* g1  = (const float*)d_in[9];
    const float* be1 = (const float*)d_in[10];
    const float* g2  = (const float*)d_in[11];
    const float* be2 = (const float*)d_in[12];
    float* out = (float*)d_out;

    float *QK, *Qh, *Kh, *Ch, *Ctx, *y, *x1, *Hf, *y2;
    float *xr, *Wqk, *Wor, *W1r, *W2r;
    cudaGetSymbolAddress((void**)&QK, g_QK);
    cudaGetSymbolAddress((void**)&Qh, g_Qh);
    cudaGetSymbolAddress((void**)&Kh, g_Kh);
    cudaGetSymbolAddress((void**)&Ch, g_Ch);
    cudaGetSymbolAddress((void**)&Ctx,g_Ctx);
    cudaGetSymbolAddress((void**)&y,  g_y);
    cudaGetSymbolAddress((void**)&x1, g_x1);
    cudaGetSymbolAddress((void**)&Hf, g_Hf);
    cudaGetSymbolAddress((void**)&y2, g_y2);
    cudaGetSymbolAddress((void**)&xr, g_xr);
    cudaGetSymbolAddress((void**)&Wqk,g_Wqk);
    cudaGetSymbolAddress((void**)&Wor,g_Wor);
    cudaGetSymbolAddress((void**)&W1r,g_W1r);
    cudaGetSymbolAddress((void**)&W2r,g_W2r);

    static bool attrs_set = false;
    if (!attrs_set) {
        cudaFuncSetAttribute(attn_fused, cudaFuncAttributeMaxDynamicSharedMemorySize, ATTN_SMEM_BYTES);
        cudaFuncSetAttribute(gemm_tc<EPI_NONE, false>,      cudaFuncAttributeMaxDynamicSharedMemorySize, GEMM_SMEM_BYTES);
        cudaFuncSetAttribute(gemm_tc<EPI_RES, false>,       cudaFuncAttributeMaxDynamicSharedMemorySize, GEMM_SMEM_BYTES);
        cudaFuncSetAttribute(gemm_tc<EPI_BIAS_GELU, true>,  cudaFuncAttributeMaxDynamicSharedMemorySize, GEMM_SMEM_BYTES);
        cudaFuncSetAttribute(gemm_tc<EPI_BIAS_RES, false>,  cudaFuncAttributeMaxDynamicSharedMemorySize, GEMM_SMEM_BYTES);
        attrs_set = true;
    }

    const int nperm = MROWS * HID;

    // ---- operand pre-rounding ----
    concat_qk_k<<<(HID * (HID / 4) + 255) / 256, 256>>>(Wq, Wk, Wqk);
    round_copy_k<<<(HID * HID / 4 + 255) / 256, 256>>>((const float4*)Wo, (float4*)Wor, HID * HID / 4);
    round_copy_k<<<(HID * MLPD / 4 + 255) / 256, 256>>>((const float4*)W1, (float4*)W1r, HID * MLPD / 4);
    round_copy_k<<<(MLPD * HID / 4 + 255) / 256, 256>>>((const float4*)W2, (float4*)W2r, MLPD * HID / 4);
    round_copy_k<<<(MROWS * HID / 4 + 255) / 256, 256>>>((const float4*)x, (float4*)xr, MROWS * HID / 4);

    // ---- QK merged GEMM: [Q|K] = xr @ [Wq|Wk] ----
    gemm_tc<EPI_NONE, false><<<dim3(2 * HID / 128, MROWS / 128), 256, GEMM_SMEM_BYTES>>>(
        xr, Wqk, QK, nullptr, nullptr, MROWS, 2 * HID, HID);

    // ---- permutes to head-major ----
    to_head_k<<<(nperm + 255) / 256, 256>>>(QK, Qh, 0);
    to_head_k<<<(nperm + 255) / 256, 256>>>(QK, Kh, HID);

    // ---- fused flash attention (K doubles as V per reference) ----
    attn_fused<<<dim3(LSEQ / 128, NHEADS_TOT), 256, ATTN_SMEM_BYTES>>>(Qh, Kh, Ch);
    from_head_k<<<(nperm + 255) / 256, 256>>>(Ch, Ctx);

    // ---- y = ctx @ Wo + x ; x1 = LN(y) (tf32-rounded) ----
    gemm_tc<EPI_RES, false><<<dim3(HID / 128, MROWS / 128), 256, GEMM_SMEM_BYTES>>>(
        Ctx, Wor, y, nullptr, x, MROWS, HID, HID);
    layernorm_rows_k<true><<<MROWS, 256>>>(y, g1, be1, x1);

    // ---- MLP ----
    gemm_tc<EPI_BIAS_GELU, true><<<dim3(MLPD / 128, MROWS / 128), 256, GEMM_SMEM_BYTES>>>(
        x1, W1r, Hf, b1, nullptr, MROWS, MLPD, HID);
    gemm_tc<EPI_BIAS_RES, false><<<dim3(HID / 128, MROWS / 128), 256, GEMM_SMEM_BYTES>>>(
        Hf, W2r, y2, b2, x1, MROWS, HID, MLPD);
    layernorm_rows_k<false><<<MROWS, 256>>>(y2, g2, be2, out);
}

// round 6
// speedup vs baseline: 3.9573x; 1.0321x over previous
#include <cuda_runtime.h>
#include <math.h>
#include <stdint.h>

#define BATCH 8
#define LSEQ  1024
#define HID   768
#define NH    12
#define DH    64
#define MLPD  3072
#define MROWS (BATCH*LSEQ)    // 8192
#define NHEADS_TOT (BATCH*NH) // 96

// ---------------- static scratch ----------------
__device__ float g_QK [(size_t)MROWS*2*HID];   // merged Q|K output
__device__ float g_Qh [MROWS*HID];
__device__ float g_Kh [MROWS*HID];
__device__ float g_Ch [MROWS*HID];
__device__ float g_Ctx[MROWS*HID];
__device__ float g_y  [MROWS*HID];
__device__ float g_x1 [MROWS*HID];
__device__ float g_Hf [(size_t)MROWS*MLPD];
__device__ float g_y2 [MROWS*HID];
// rounded operands
__device__ float g_xr [MROWS*HID];
__device__ float g_Wqk[HID*2*HID];
__device__ float g_Wor[HID*HID];
__device__ float g_W1r[HID*MLPD];
__device__ float g_W2r[MLPD*HID];

// ---------------- helpers ----------------
__device__ __forceinline__ float gelu_f(float v) {
    return 0.5f * v * (1.0f + erff(v * 0.7071067811865475f));
}

__device__ __forceinline__ uint32_t f2tf32(float f) {
    uint32_t u;
    asm("cvt.rna.tf32.f32 %0, %1;" : "=r"(u) : "f"(f));
    return u;
}
__device__ __forceinline__ float rndtf(float f) { return __uint_as_float(f2tf32(f)); }

__device__ __forceinline__ void mma_tf32(float* d, const uint32_t* a, const uint32_t* b) {
    asm volatile(
        "mma.sync.aligned.m16n8k8.row.col.f32.tf32.tf32.f32 "
        "{%0,%1,%2,%3}, {%4,%5,%6,%7}, {%8,%9}, {%0,%1,%2,%3};\n"
        : "+f"(d[0]), "+f"(d[1]), "+f"(d[2]), "+f"(d[3])
        : "r"(a[0]), "r"(a[1]), "r"(a[2]), "r"(a[3]),
          "r"(b[0]), "r"(b[1]));
}

__device__ __forceinline__ void cp16(uint32_t dst, const void* src) {
    asm volatile("cp.async.cg.shared.global [%0], [%1], 16;\n" :: "r"(dst), "l"(src));
}
__device__ __forceinline__ void cp_commit() {
    asm volatile("cp.async.commit_group;\n");
}
template<int N>
__device__ __forceinline__ void cp_wait() {
    asm volatile("cp.async.wait_group %0;\n" :: "n"(N));
}

enum { EPI_NONE = 0, EPI_RES = 1, EPI_BIAS_GELU = 2, EPI_BIAS_RES = 3 };

// ---------------- TF32 tensor-core GEMM: C = A(MxK) @ B(KxN) ----------------
// 128x128 CTA tile, BK=16, 4-stage cp.async pipeline. Operands pre-rounded
// to tf32 (RNA) in gmem. __launch_bounds__(256,2) guarantees 2 CTAs/SM.
#define AS_STR 20
#define BS_STR 136
#define STAGES 4
#define GEMM_SMEM_BYTES (STAGES * (128 * AS_STR + 16 * BS_STR) * 4)

template<int EPI, bool ROUND_OUT>
__global__ __launch_bounds__(256, 2) void gemm_tc(
    const float* __restrict__ A, const float* __restrict__ B, float* __restrict__ C,
    const float* __restrict__ bias, const float* __restrict__ res,
    int M, int N, int K)
{
    extern __shared__ uint32_t dynsmem[];
    uint32_t* As = dynsmem;                            // [STAGES][128][AS_STR]
    uint32_t* Bs = dynsmem + STAGES * 128 * AS_STR;    // [STAGES][16][BS_STR]
    const uint32_t sA = (uint32_t)__cvta_generic_to_shared(As);
    const uint32_t sB = (uint32_t)__cvta_generic_to_shared(Bs);

    const int tid  = threadIdx.x;
    const int lane = tid & 31;
    const int warp = tid >> 5;
    const int grp  = lane >> 2;
    const int tg   = lane & 3;
    const int wm   = (warp >> 2) * 64;
    const int wn   = (warp & 3) * 32;
    const int bx   = blockIdx.x;
    const int by   = blockIdx.y;

    const int ar0 = tid >> 2,  ac0 = (tid & 3) * 4;
    const int ar1 = ar0 + 64;
    const int br0 = tid >> 5,  bc0 = (tid & 31) * 4;
    const int br1 = br0 + 8;

    const float* Abase = A + (size_t)(by * 128) * K;
    const float* Bbase = B + bx * 128;

    float acc[4][4][4];
    #pragma unroll
    for (int i = 0; i < 4; i++)
        #pragma unroll
        for (int j = 0; j < 4; j++)
            #pragma unroll
            for (int r = 0; r < 4; r++) acc[i][j][r] = 0.0f;

    const int ntiles = K >> 4;

    auto issue = [&](int t) {
        const int st = t & (STAGES - 1);
        const int k0 = t * 16;
        const uint32_t aoff = sA + (uint32_t)(st * 128 * AS_STR) * 4;
        const uint32_t boff = sB + (uint32_t)(st * 16 * BS_STR) * 4;
        cp16(aoff + (uint32_t)(ar0 * AS_STR + ac0) * 4, Abase + (size_t)ar0 * K + k0 + ac0);
        cp16(aoff + (uint32_t)(ar1 * AS_STR + ac0) * 4, Abase + (size_t)ar1 * K + k0 + ac0);
        cp16(boff + (uint32_t)(br0 * BS_STR + bc0) * 4, Bbase + (size_t)(k0 + br0) * N + bc0);
        cp16(boff + (uint32_t)(br1 * BS_STR + bc0) * 4, Bbase + (size_t)(k0 + br1) * N + bc0);
        cp_commit();
    };

    #pragma unroll
    for (int t = 0; t < STAGES - 1; t++) issue(t);

    for (int t = 0; t < ntiles; t++) {
        cp_wait<STAGES - 2>();
        __syncthreads();

        const int cur = t & (STAGES - 1);
        const uint32_t* Ac = As + cur * 128 * AS_STR;
        const uint32_t* Bc = Bs + cur * 16 * BS_STR;

        #pragma unroll
        for (int kk = 0; kk < 16; kk += 8) {
            uint32_t a[4][4], b[4][2];
            #pragma unroll
            for (int mt = 0; mt < 4; mt++) {
                const int r = wm + mt * 16 + grp;
                a[mt][0] = Ac[r * AS_STR + kk + tg];
                a[mt][1] = Ac[(r + 8) * AS_STR + kk + tg];
                a[mt][2] = Ac[r * AS_STR + kk + tg + 4];
                a[mt][3] = Ac[(r + 8) * AS_STR + kk + tg + 4];
            }
            #pragma unroll
            for (int nt = 0; nt < 4; nt++) {
                const int c = wn + nt * 8 + grp;
                b[nt][0] = Bc[(kk + tg) * BS_STR + c];
                b[nt][1] = Bc[(kk + tg + 4) * BS_STR + c];
            }
            #pragma unroll
            for (int mt = 0; mt < 4; mt++)
                #pragma unroll
                for (int nt = 0; nt < 4; nt++)
                    mma_tf32(acc[mt][nt], a[mt], b[nt]);
        }

        if (t + STAGES - 1 < ntiles) issue(t + STAGES - 1);
        else cp_commit();
    }

    #pragma unroll
    for (int mt = 0; mt < 4; mt++) {
        #pragma unroll
        for (int nt = 0; nt < 4; nt++) {
            const int r0 = by * 128 + wm + mt * 16 + grp;
            const int c0 = bx * 128 + wn + nt * 8 + tg * 2;
            float v0 = acc[mt][nt][0], v1 = acc[mt][nt][1];
            float v2 = acc[mt][nt][2], v3 = acc[mt][nt][3];
            if (EPI == EPI_RES) {
                const float2 r0v = *(const float2*)&res[(size_t)r0 * N + c0];
                const float2 r1v = *(const float2*)&res[(size_t)(r0 + 8) * N + c0];
                v0 += r0v.x; v1 += r0v.y; v2 += r1v.x; v3 += r1v.y;
            }
            if (EPI == EPI_BIAS_GELU) {
                const float2 bv = *(const float2*)&bias[c0];
                v0 = gelu_f(v0 + bv.x); v1 = gelu_f(v1 + bv.y);
                v2 = gelu_f(v2 + bv.x); v3 = gelu_f(v3 + bv.y);
            }
            if (EPI == EPI_BIAS_RES) {
                const float2 bv = *(const float2*)&bias[c0];
                const float2 r0v = *(const float2*)&res[(size_t)r0 * N + c0];
                const float2 r1v = *(const float2*)&res[(size_t)(r0 + 8) * N + c0];
                v0 += bv.x + r0v.x; v1 += bv.y + r0v.y;
                v2 += bv.x + r1v.x; v3 += bv.y + r1v.y;
            }
            if (ROUND_OUT) {
                v0 = rndtf(v0); v1 = rndtf(v1); v2 = rndtf(v2); v3 = rndtf(v3);
            }
            float2 w0 = {v0, v1}, w1 = {v2, v3};
            *(float2*)&C[(size_t)r0 * N + c0] = w0;
            *(float2*)&C[(size_t)(r0 + 8) * N + c0] = w1;
        }
    }
}

// ---------------- merged operand pre-rounding ----------------
// One grid-stride kernel rounds all weights (and builds [Wq|Wk] concat).
#define NQK (HID*HID/4)
#define NWO (HID*HID/4)
#define NW1 (HID*MLPD/4)
#define NW2 (MLPD*HID/4)
#define NWTOT (NQK + NWO + NW1 + NW2)

__device__ __forceinline__ float4 rnd4(float4 v) {
    v.x = rndtf(v.x); v.y = rndtf(v.y); v.z = rndtf(v.z); v.w = rndtf(v.w);
    return v;
}

__global__ void round_weights_k(const float* __restrict__ Wq, const float* __restrict__ Wk,
                                const float* __restrict__ Wo, const float* __restrict__ W1,
                                const float* __restrict__ W2) {
    int i = blockIdx.x * blockDim.x + threadIdx.x;
    if (i >= NWTOT) return;
    if (i < NQK) {
        int k = i / (HID / 4), c = (i % (HID / 4)) * 4;
        float4 q  = rnd4(*(const float4*)(Wq + (size_t)k * HID + c));
        float4 kk = rnd4(*(const float4*)(Wk + (size_t)k * HID + c));
        *(float4*)(g_Wqk + (size_t)k * (2 * HID) + c) = q;
        *(float4*)(g_Wqk + (size_t)k * (2 * HID) + HID + c) = kk;
        return;
    }
    i -= NQK;
    if (i < NWO) { ((float4*)g_Wor)[i] = rnd4(((const float4*)Wo)[i]); return; }
    i -= NWO;
    if (i < NW1) { ((float4*)g_W1r)[i] = rnd4(((const float4*)W1)[i]); return; }
    i -= NW1;
    ((float4*)g_W2r)[i] = rnd4(((const float4*)W2)[i]);
}

__global__ void round_x_k(const float4* __restrict__ in, float4* __restrict__ out, int n4) {
    int i = blockIdx.x * blockDim.x + threadIdx.x;
    if (i >= n4) return;
    out[i] = rnd4(in[i]);
}

// ---------------- permutes ----------------
// merged: writes both Qh and Kh from the QK buffer [MROWS][2*HID]
__global__ void to_head2_k(const float* __restrict__ QK,
                           float* __restrict__ Qh, float* __restrict__ Kh) {
    int idx = blockIdx.x * blockDim.x + threadIdx.x;
    if (idx >= MROWS * HID) return;
    int d = idx & 63;
    int l = (idx >> 6) & 1023;
    int z = idx >> 16;
    int n = z % NH, b = z / NH;
    const size_t src = (size_t)(b * LSEQ + l) * (2 * HID) + d * NH + n;
    Qh[idx] = QK[src];
    Kh[idx] = QK[src + HID];
}

__global__ void from_head_k(const float* __restrict__ Xh, float* __restrict__ X) {
    int idx = blockIdx.x * blockDim.x + threadIdx.x;
    if (idx >= MROWS * HID) return;
    int h = idx % HID;
    int row = idx / HID;
    int l = row & 1023, b = row >> 10;
    int d = h / NH, n = h % NH;
    X[idx] = rndtf(Xh[((size_t)(b * NH + n) * LSEQ + l) * DH + d]);
}

// ---------------- fused flash attention (TF32 mma) ----------------
#define QS_STR 68
#define KS_STR 68
#define PS_STR 132
#define ATTN_SMEM_WORDS (128*QS_STR + 128*KS_STR + 128*PS_STR + 128 + 128 + 512 + 512)
#define ATTN_SMEM_BYTES (ATTN_SMEM_WORDS * 4)

__global__ __launch_bounds__(256) void attn_fused(
    const float* __restrict__ Qh, const float* __restrict__ Kh, float* __restrict__ Ch)
{
    extern __shared__ uint32_t sm[];
    uint32_t* Qs = sm;
    uint32_t* Ks = Qs + 128 * QS_STR;
    uint32_t* Ps = Ks + 128 * KS_STR;
    float* Mrow  = (float*)(Ps + 128 * PS_STR);
    float* Srow  = Mrow + 128;
    float* red1  = Srow + 128;
    float* red2  = red1 + 512;

    const int z   = blockIdx.y;
    const int l0  = blockIdx.x * 128;
    const int tid = threadIdx.x;
    const int lane = tid & 31;
    const int warp = tid >> 5;
    const int grp  = lane >> 2;
    const int tg   = lane & 3;
    const int wm   = (warp >> 2) * 64;
    const int wn   = (warp & 3) * 32;
    const int wn2  = (warp & 3) * 16;
    const int wc   = warp & 3;

    const float* Qbase = Qh + ((size_t)z * LSEQ + l0) * DH;
    const float* Kbase = Kh + (size_t)z * LSEQ * DH;

    if (tid < 128) { Mrow[tid] = -3.0e38f; Srow[tid] = 0.0f; }

    #pragma unroll
    for (int i = 0; i < 8; i++) {
        int f = tid + 256 * i;
        int r = f >> 4, c = (f & 15) * 4;
        float4 q = *(const float4*)(Qbase + r * DH + c);
        Qs[r * QS_STR + c + 0] = f2tf32(0.125f * q.x);
        Qs[r * QS_STR + c + 1] = f2tf32(0.125f * q.y);
        Qs[r * QS_STR + c + 2] = f2tf32(0.125f * q.z);
        Qs[r * QS_STR + c + 3] = f2tf32(0.125f * q.w);
    }

    float acc_o[4][2][4];
    #pragma unroll
    for (int i = 0; i < 4; i++)
        #pragma unroll
        for (int j = 0; j < 2; j++)
            #pragma unroll
            for (int r = 0; r < 4; r++) acc_o[i][j][r] = 0.0f;

    __syncthreads();

    for (int mtile = 0; mtile < LSEQ / 128; mtile++) {
        const float* Kt = Kbase + (size_t)mtile * 128 * DH;
        #pragma unroll
        for (int i = 0; i < 8; i++) {
            int f = tid + 256 * i;
            int r = f >> 4, c = (f & 15) * 4;
            float4 k4 = *(const float4*)(Kt + r * DH + c);
            Ks[r * KS_STR + c + 0] = f2tf32(k4.x);
            Ks[r * KS_STR + c + 1] = f2tf32(k4.y);
            Ks[r * KS_STR + c + 2] = f2tf32(k4.z);
            Ks[r * KS_STR + c + 3] = f2tf32(k4.w);
        }
        __syncthreads();

        float s[4][4][4];
        #pragma unroll
        for (int i = 0; i < 4; i++)
            #pragma unroll
            for (int j = 0; j < 4; j++)
                #pragma unroll
                for (int r = 0; r < 4; r++) s[i][j][r] = 0.0f;

        #pragma unroll
        for (int kk = 0; kk < DH; kk += 8) {
            uint32_t a[4][4], b[4][2];
            #pragma unroll
            for (int mt = 0; mt < 4; mt++) {
                const int r = wm + mt * 16 + grp;
                a[mt][0] = Qs[r * QS_STR + kk + tg];
                a[mt][1] = Qs[(r + 8) * QS_STR + kk + tg];
                a[mt][2] = Qs[r * QS_STR + kk + tg + 4];
                a[mt][3] = Qs[(r + 8) * QS_STR + kk + tg + 4];
            }
            #pragma unroll
            for (int nt = 0; nt < 4; nt++) {
                const int c = wn + nt * 8 + grp;
                b[nt][0] = Ks[c * KS_STR + kk + tg];
                b[nt][1] = Ks[c * KS_STR + kk + tg + 4];
            }
            #pragma unroll
            for (int mt = 0; mt < 4; mt++)
                #pragma unroll
                for (int nt = 0; nt < 4; nt++)
                    mma_tf32(s[mt][nt], a[mt], b[nt]);
        }

        #pragma unroll
        for (int mt = 0; mt < 4; mt++) {
            float mlo = -3.0e38f, mhi = -3.0e38f;
            #pragma unroll
            for (int nt = 0; nt < 4; nt++) {
                mlo = fmaxf(mlo, fmaxf(s[mt][nt][0], s[mt][nt][1]));
                mhi = fmaxf(mhi, fmaxf(s[mt][nt][2], s[mt][nt][3]));
            }
            mlo = fmaxf(mlo, __shfl_xor_sync(0xffffffffu, mlo, 1));
            mlo = fmaxf(mlo, __shfl_xor_sync(0xffffffffu, mlo, 2));
            mhi = fmaxf(mhi, __shfl_xor_sync(0xffffffffu, mhi, 1));
            mhi = fmaxf(mhi, __shfl_xor_sync(0xffffffffu, mhi, 2));
            if (tg == 0) {
                red1[(wm + mt * 16 + grp) * 4 + wc]     = mlo;
                red1[(wm + mt * 16 + grp + 8) * 4 + wc] = mhi;
            }
        }
        __syncthreads();

        float newlo[4], newhi[4], scllo[4], sclhi[4];
        #pragma unroll
        for (int mt = 0; mt < 4; mt++) {
            const int rlo = wm + mt * 16 + grp;
            const int rhi = rlo + 8;
            float4 v1 = *(const float4*)&red1[rlo * 4];
            float4 v2 = *(const float4*)&red1[rhi * 4];
            float tlo = fmaxf(fmaxf(v1.x, v1.y), fmaxf(v1.z, v1.w));
            float thi = fmaxf(fmaxf(v2.x, v2.y), fmaxf(v2.z, v2.w));
            float oldlo = Mrow[rlo], oldhi = Mrow[rhi];
            float nlo = fmaxf(oldlo, tlo), nhi = fmaxf(oldhi, thi);
            newlo[mt] = nlo; newhi[mt] = nhi;
            scllo[mt] = __expf(oldlo - nlo);
            sclhi[mt] = __expf(oldhi - nhi);

            float pslo = 0.0f, pshi = 0.0f;
            #pragma unroll
            for (int nt = 0; nt < 4; nt++) {
                const int c = wn + nt * 8 + 2 * tg;
                float p0 = __expf(s[mt][nt][0] - nlo);
                float p1 = __expf(s[mt][nt][1] - nlo);
                float p2 = __expf(s[mt][nt][2] - nhi);
                float p3 = __expf(s[mt][nt][3] - nhi);
                Ps[rlo * PS_STR + c]     = f2tf32(p0);
                Ps[rlo * PS_STR + c + 1] = f2tf32(p1);
                Ps[rhi * PS_STR + c]     = f2tf32(p2);
                Ps[rhi * PS_STR + c + 1] = f2tf32(p3);
                pslo += p0 + p1;
                pshi += p2 + p3;
            }
            pslo += __shfl_xor_sync(0xffffffffu, pslo, 1);
            pslo += __shfl_xor_sync(0xffffffffu, pslo, 2);
            pshi += __shfl_xor_sync(0xffffffffu, pshi, 1);
            pshi += __shfl_xor_sync(0xffffffffu, pshi, 2);
            if (tg == 0) {
                red2[rlo * 4 + wc] = pslo;
                red2[rhi * 4 + wc] = pshi;
            }
            #pragma unroll
            for (int nt2 = 0; nt2 < 2; nt2++) {
                acc_o[mt][nt2][0] *= scllo[mt];
                acc_o[mt][nt2][1] *= scllo[mt];
                acc_o[mt][nt2][2] *= sclhi[mt];
                acc_o[mt][nt2][3] *= sclhi[mt];
            }
        }
        __syncthreads();

        if (wc == 0 && tg == 0) {
            #pragma unroll
            for (int mt = 0; mt < 4; mt++) {
                const int rlo = wm + mt * 16 + grp;
                const int rhi = rlo + 8;
                float4 w1 = *(const float4*)&red2[rlo * 4];
                float4 w2 = *(const float4*)&red2[rhi * 4];
                Srow[rlo] = Srow[rlo] * scllo[mt] + (w1.x + w1.y + w1.z + w1.w);
                Srow[rhi] = Srow[rhi] * sclhi[mt] + (w2.x + w2.y + w2.z + w2.w);
                Mrow[rlo] = newlo[mt];
                Mrow[rhi] = newhi[mt];
            }
        }

        #pragma unroll
        for (int kk = 0; kk < 128; kk += 8) {
            uint32_t a[4][4], b[2][2];
            #pragma unroll
            for (int mt = 0; mt < 4; mt++) {
                const int r = wm + mt * 16 + grp;
                a[mt][0] = Ps[r * PS_STR + kk + tg];
                a[mt][1] = Ps[(r + 8) * PS_STR + kk + tg];
                a[mt][2] = Ps[r * PS_STR + kk + tg + 4];
                a[mt][3] = Ps[(r + 8) * PS_STR + kk + tg + 4];
            }
            #pragma unroll
            for (int nt2 = 0; nt2 < 2; nt2++) {
                const int c = wn2 + nt2 * 8 + grp;
                b[nt2][0] = Ks[(kk + tg) * KS_STR + c];
                b[nt2][1] = Ks[(kk + tg + 4) * KS_STR + c];
            }
            #pragma unroll
            for (int mt = 0; mt < 4; mt++)
                #pragma unroll
                for (int nt2 = 0; nt2 < 2; nt2++)
                    mma_tf32(acc_o[mt][nt2], a[mt], b[nt2]);
        }
        __syncthreads();
    }

    #pragma unroll
    for (int mt = 0; mt < 4; mt++) {
        const int rlo = wm + mt * 16 + grp;
        const int rhi = rlo + 8;
        const float ilo = 1.0f / Srow[rlo];
        const float ihi = 1.0f / Srow[rhi];
        #pragma unroll
        for (int nt2 = 0; nt2 < 2; nt2++) {
            const int c = wn2 + nt2 * 8 + 2 * tg;
            float2 o0 = {acc_o[mt][nt2][0] * ilo, acc_o[mt][nt2][1] * ilo};
            float2 o1 = {acc_o[mt][nt2][2] * ihi, acc_o[mt][nt2][3] * ihi};
            *(float2*)&Ch[((size_t)z * LSEQ + l0 + rlo) * DH + c] = o0;
            *(float2*)&Ch[((size_t)z * LSEQ + l0 + rhi) * DH + c] = o1;
        }
    }
}

// ---------------- layernorm ----------------
template<bool RND>
__global__ __launch_bounds__(256) void layernorm_rows_k(
    const float* __restrict__ X, const float* __restrict__ g,
    const float* __restrict__ be, float* __restrict__ Y)
{
    const int row = blockIdx.x;
    const float* x = X + (size_t)row * HID;
    float* y = Y + (size_t)row * HID;
    const int tid = threadIdx.x;
    __shared__ float shs[8], shss[8];

    float s = 0.0f, ss = 0.0f;
    for (int c = tid; c < HID; c += 256) {
        float v = x[c];
        s += v;
        ss = fmaf(v, v, ss);
    }
    #pragma unroll
    for (int o = 16; o; o >>= 1) {
        s  += __shfl_xor_sync(0xffffffffu, s, o);
        ss += __shfl_xor_sync(0xffffffffu, ss, o);
    }
    if ((tid & 31) == 0) { shs[tid >> 5] = s; shss[tid >> 5] = ss; }
    __syncthreads();
    if (tid == 0) {
        float a = 0.0f, b = 0.0f;
        #pragma unroll
        for (int i = 0; i < 8; i++) { a += shs[i]; b += shss[i]; }
        shs[0] = a; shss[0] = b;
    }
    __syncthreads();
    const float mu  = shs[0]  * (1.0f / HID);
    const float var = shss[0] * (1.0f / HID) - mu * mu;
    const float inv = rsqrtf(var + 1e-5f);
    for (int c = tid; c < HID; c += 256) {
        float v = (x[c] - mu) * inv * g[c] + be[c];
        y[c] = RND ? rndtf(v) : v;
    }
}

// ---------------- host launch ----------------
extern "C" void kernel_launch(void* const* d_in, const int* in_sizes, int n_in,
                              void* d_out, int out_size)
{
    const float* x   = (const float*)d_in[0];
    const float* Wq  = (const float*)d_in[1];
    const float* Wk  = (const float*)d_in[2];
    // d_in[3] = Wv: unused (ctx contracts with K in the reference)
    const float* Wo  = (const float*)d_in[4];
    const float* W1  = (const float*)d_in[5];
    const float* b1  = (const float*)d_in[6];
    const float* W2  = (const float*)d_in[7];
    const float* b2  = (const float*)d_in[8];
    const float* g1  = (const float*)d_in[9];
    const float* be1 = (const float*)d_in[10];
    const float* g2  = (const float*)d_in[11];
    const float* be2 = (const float*)d_in[12];
    float* out = (float*)d_out;

    float *QK, *Qh, *Kh, *Ch, *Ctx, *y, *x1, *Hf, *y2;
    float *xr, *Wqk, *Wor, *W1r, *W2r;
    cudaGetSymbolAddress((void**)&QK, g_QK);
    cudaGetSymbolAddress((void**)&Qh, g_Qh);
    cudaGetSymbolAddress((void**)&Kh, g_Kh);
    cudaGetSymbolAddress((void**)&Ch, g_Ch);
    cudaGetSymbolAddress((void**)&Ctx,g_Ctx);
    cudaGetSymbolAddress((void**)&y,  g_y);
    cudaGetSymbolAddress((void**)&x1, g_x1);
    cudaGetSymbolAddress((void**)&Hf, g_Hf);
    cudaGetSymbolAddress((void**)&y2, g_y2);
    cudaGetSymbolAddress((void**)&xr, g_xr);
    cudaGetSymbolAddress((void**)&Wqk,g_Wqk);
    cudaGetSymbolAddress((void**)&Wor,g_Wor);
    cudaGetSymbolAddress((void**)&W1r,g_W1r);
    cudaGetSymbolAddress((void**)&W2r,g_W2r);

    static bool attrs_set = false;
    if (!attrs_set) {
        cudaFuncSetAttribute(attn_fused, cudaFuncAttributeMaxDynamicSharedMemorySize, ATTN_SMEM_BYTES);
        cudaFuncSetAttribute(gemm_tc<EPI_NONE, false>,      cudaFuncAttributeMaxDynamicSharedMemorySize, GEMM_SMEM_BYTES);
        cudaFuncSetAttribute(gemm_tc<EPI_RES, false>,       cudaFuncAttributeMaxDynamicSharedMemorySize, GEMM_SMEM_BYTES);
        cudaFuncSetAttribute(gemm_tc<EPI_BIAS_GELU, true>,  cudaFuncAttributeMaxDynamicSharedMemorySize, GEMM_SMEM_BYTES);
        cudaFuncSetAttribute(gemm_tc<EPI_BIAS_RES, false>,  cudaFuncAttributeMaxDynamicSharedMemorySize, GEMM_SMEM_BYTES);
        attrs_set = true;
    }

    const int nperm = MROWS * HID;

    // ---- operand pre-rounding (RNA->tf32), merged kernels ----
    round_weights_k<<<(NWTOT + 255) / 256, 256>>>(Wq, Wk, Wo, W1, W2);
    round_x_k<<<(MROWS * HID / 4 + 255) / 256, 256>>>((const float4*)x, (float4*)xr, MROWS * HID / 4);

    // ---- QK merged GEMM: [Q|K] = xr @ [Wq|Wk] ----
    gemm_tc<EPI_NONE, false><<<dim3(2 * HID / 128, MROWS / 128), 256, GEMM_SMEM_BYTES>>>(
        xr, Wqk, QK, nullptr, nullptr, MROWS, 2 * HID, HID);

    // ---- permute to head-major (both Q and K in one pass) ----
    to_head2_k<<<(nperm + 255) / 256, 256>>>(QK, Qh, Kh);

    // ---- fused flash attention (K doubles as V per reference) ----
    attn_fused<<<dim3(LSEQ / 128, NHEADS_TOT), 256, ATTN_SMEM_BYTES>>>(Qh, Kh, Ch);
    from_head_k<<<(nperm + 255) / 256, 256>>>(Ch, Ctx);

    // ---- y = ctx @ Wo + x ; x1 = LN(y) (tf32-rounded) ----
    gemm_tc<EPI_RES, false><<<dim3(HID / 128, MROWS / 128), 256, GEMM_SMEM_BYTES>>>(
        Ctx, Wor, y, nullptr, x, MROWS, HID, HID);
    layernorm_rows_k<true><<<MROWS, 256>>>(y, g1, be1, x1);

    // ---- MLP ----
    gemm_tc<EPI_BIAS_GELU, true><<<dim3(MLPD / 128, MROWS / 128), 256, GEMM_SMEM_BYTES>>>(
        x1, W1r, Hf, b1, nullptr, MROWS, MLPD, HID);
    gemm_tc<EPI_BIAS_RES, false><<<dim3(HID / 128, MROWS / 128), 256, GEMM_SMEM_BYTES>>>(
        Hf, W2r, y2, b2, x1, MROWS, HID, MLPD);
    layernorm_rows_k<false><<<MROWS, 256>>>(y2, g2, be2, out);
}